// round 4
// baseline (speedup 1.0000x reference)
#include <cuda_runtime.h>
#include <cuda_bf16.h>
#include <math_constants.h>
#include <cstdint>

// Problem constants (reference: N=100000, E=1200000, all dims 128)
#define MAXN 100000
#define MAXE 1200000
#define MAXE2 (MAXE + MAXN)

// Scratch (device globals — allocation-free rule)
__device__ __align__(16) float g_xw[MAXN * 128];
__device__ __align__(16) float g_h[MAXN * 128];
__device__ __align__(16) float g_ssrc[MAXN * 4];
__device__ __align__(16) float g_sdst[MAXN * 4];
__device__ __align__(16) float g_alpha[MAXE2 * 4];

__device__ int g_counts[MAXN];
__device__ int g_cursor[MAXN];
__device__ int g_rowptr[MAXN + 1];
__device__ int g_csr[MAXE2];

// Pre-split weights: tf32 hi/lo (stored as fp32 bit patterns), transposed [n][k]
__device__ __align__(16) float g_Whi32[3 * 128 * 128];
__device__ __align__(16) float g_Wlo32[3 * 128 * 128];

// ---------------------------------------------------------------------------
__device__ __forceinline__ float to_tf32(float x) {
    uint32_t u;
    asm("cvt.rna.tf32.f32 %0, %1;" : "=r"(u) : "f"(x));
    return __uint_as_float(u);
}

__device__ __forceinline__ void mma_tf32(float* c, float2 a_lo, float2 a_hi, float2 b) {
    // a_lo = {a0 (row g,   col q), a2 (row g,   col q+4)}
    // a_hi = {a1 (row g+8, col q), a3 (row g+8, col q+4)}
    // b    = {b0 (k q, n g),       b1 (k q+4, n g)}
    asm("mma.sync.aligned.m16n8k8.row.col.f32.tf32.tf32.f32 "
        "{%0,%1,%2,%3}, {%4,%5,%6,%7}, {%8,%9}, {%0,%1,%2,%3};"
        : "+f"(c[0]), "+f"(c[1]), "+f"(c[2]), "+f"(c[3])
        : "r"(__float_as_uint(a_lo.x)), "r"(__float_as_uint(a_hi.x)),
          "r"(__float_as_uint(a_lo.y)), "r"(__float_as_uint(a_hi.y)),
          "r"(__float_as_uint(b.x)),    "r"(__float_as_uint(b.y)));
}

// Swizzled float2 slot: tile stored as float2[rows][64]; pair slot f holds
// k-columns (8*(f/4) + f%4, +4). Swizzle bits 2..3 of f by (row & 3).
__device__ __forceinline__ int slot_idx(int row, int f) {
    return row * 64 + (f ^ ((row & 3) << 2));
}

// ---------------------------------------------------------------------------
// Weight prep: W[k][n] fp32 -> tf32 hi/lo, transposed to [n][k]
// ---------------------------------------------------------------------------
__global__ void prep_w_k(const float* __restrict__ W0, const float* __restrict__ W1,
                         const float* __restrict__ W2)
{
    int i = blockIdx.x * blockDim.x + threadIdx.x;
    if (i >= 3 * 16384) return;
    int l = i >> 14, r = i & 16383;
    int k = r >> 7, nn = r & 127;
    const float* W = (l == 0) ? W0 : (l == 1) ? W1 : W2;
    float x = W[k * 128 + nn];
    float hi = to_tf32(x);
    g_Whi32[l * 16384 + nn * 128 + k] = hi;
    g_Wlo32[l * 16384 + nn * 128 + k] = to_tf32(x - hi);
}

// ---------------------------------------------------------------------------
// 3xTF32 GEMM: g_xw[64 rows/block, 128] = A @ W, with fused score epilogue
// (g_ssrc/g_sdst). Block: 128 threads (4 warps, each 32 rows x 64 cols).
// Smem: A_hi/A_lo (64x128) + W_hi/W_lo (128x128) = 192 KB, loaded once.
// ---------------------------------------------------------------------------
__global__ __launch_bounds__(128) void gemm_tf32_k(
    const float* __restrict__ A,
    const float* __restrict__ Whi, const float* __restrict__ Wlo,
    const float* __restrict__ as_, const float* __restrict__ ad_, int n)
{
    extern __shared__ float2 sm2[];
    float2* sAhi = sm2;                 // 64*64 float2
    float2* sAlo = sm2 + 64 * 64;
    float2* sWhi = sm2 + 2 * 64 * 64;   // 128*64 float2
    float2* sWlo = sm2 + 2 * 64 * 64 + 128 * 64;

    int tid = threadIdx.x;
    int wid = tid >> 5, lane = tid & 31;
    int row0 = blockIdx.x * 64;

    // Fill W tiles: 128 rows x 16 k-groups, both hi & lo
    #pragma unroll
    for (int it = 0; it < 16; it++) {
        int id = tid + it * 128;            // 0..2047
        int nr = id >> 4, g = id & 15;
        const float4* ph = (const float4*)(Whi + nr * 128 + g * 8);
        const float4* pl = (const float4*)(Wlo + nr * 128 + g * 8);
        float4 h1 = ph[0], h2 = ph[1];
        float4 l1 = pl[0], l2 = pl[1];
        sWhi[slot_idx(nr, 4 * g + 0)] = make_float2(h1.x, h2.x);
        sWhi[slot_idx(nr, 4 * g + 1)] = make_float2(h1.y, h2.y);
        sWhi[slot_idx(nr, 4 * g + 2)] = make_float2(h1.z, h2.z);
        sWhi[slot_idx(nr, 4 * g + 3)] = make_float2(h1.w, h2.w);
        sWlo[slot_idx(nr, 4 * g + 0)] = make_float2(l1.x, l2.x);
        sWlo[slot_idx(nr, 4 * g + 1)] = make_float2(l1.y, l2.y);
        sWlo[slot_idx(nr, 4 * g + 2)] = make_float2(l1.z, l2.z);
        sWlo[slot_idx(nr, 4 * g + 3)] = make_float2(l1.w, l2.w);
    }
    // Fill A tiles with tf32 split: 64 rows x 16 k-groups
    #pragma unroll
    for (int it = 0; it < 8; it++) {
        int id = tid + it * 128;            // 0..1023
        int r = id >> 4, g = id & 15;
        int grow = row0 + r;
        float4 v1 = make_float4(0.f, 0.f, 0.f, 0.f), v2 = v1;
        if (grow < n) {
            const float4* p = (const float4*)(A + (size_t)grow * 128 + g * 8);
            v1 = __ldg(p); v2 = __ldg(p + 1);
        }
        float h[8], l[8];
        float vv[8] = {v1.x, v1.y, v1.z, v1.w, v2.x, v2.y, v2.z, v2.w};
        #pragma unroll
        for (int c = 0; c < 8; c++) {
            h[c] = to_tf32(vv[c]);
            l[c] = to_tf32(vv[c] - h[c]);
        }
        #pragma unroll
        for (int c = 0; c < 4; c++) {
            sAhi[slot_idx(r, 4 * g + c)] = make_float2(h[c], h[c + 4]);
            sAlo[slot_idx(r, 4 * g + c)] = make_float2(l[c], l[c + 4]);
        }
    }
    __syncthreads();

    int q = lane & 3, g4 = lane >> 2;
    int wr = wid >> 1, wc = wid & 1;     // warp: rows wr*32.., cols wc*64..

    float acc[2][8][4];
    #pragma unroll
    for (int mt = 0; mt < 2; mt++)
        #pragma unroll
        for (int nt = 0; nt < 8; nt++)
            #pragma unroll
            for (int i = 0; i < 4; i++) acc[mt][nt][i] = 0.f;

    #pragma unroll
    for (int ks = 0; ks < 16; ks++) {
        int sx = 4 * (ks ^ (g4 & 3)) + q;     // swizzled f (row&3 == g4&3 for all operand rows)
        float2 ah[2][2], al[2][2];
        #pragma unroll
        for (int mt = 0; mt < 2; mt++) {
            int r0 = wr * 32 + mt * 16 + g4;
            ah[mt][0] = sAhi[r0 * 64 + sx];
            ah[mt][1] = sAhi[(r0 + 8) * 64 + sx];
            al[mt][0] = sAlo[r0 * 64 + sx];
            al[mt][1] = sAlo[(r0 + 8) * 64 + sx];
        }
        #pragma unroll
        for (int nt = 0; nt < 8; nt++) {
            int nr = wc * 64 + nt * 8 + g4;
            float2 bh = sWhi[nr * 64 + sx];
            float2 bl = sWlo[nr * 64 + sx];
            #pragma unroll
            for (int mt = 0; mt < 2; mt++) {
                mma_tf32(acc[mt][nt], ah[mt][0], ah[mt][1], bh);   // hi*hi
                mma_tf32(acc[mt][nt], al[mt][0], al[mt][1], bh);   // lo*hi
                mma_tf32(acc[mt][nt], ah[mt][0], ah[mt][1], bl);   // hi*lo
            }
        }
    }

    // Epilogue: write xw (float2, 32B-sector coalesced) + fused attn scores.
    // c layout: c0: (row, col), c1: (row, col+1), c2: (row+8, col), c3: (row+8, col+1)
    // with row = wr*32 + mt*16 + g4, col = wc*64 + nt*8 + q*2.
    float ps[2][2][2] = {}, pd[2][2][2] = {};   // [mt][rowsel][head-in-warp]
    #pragma unroll
    for (int mt = 0; mt < 2; mt++) {
        #pragma unroll
        for (int nt = 0; nt < 8; nt++) {
            int col = wc * 64 + nt * 8 + q * 2;
            float a0 = __ldg(as_ + col), a1 = __ldg(as_ + col + 1);
            float d0 = __ldg(ad_ + col), d1 = __ldg(ad_ + col + 1);
            int hs = nt >> 2;
            ps[mt][0][hs] += acc[mt][nt][0] * a0 + acc[mt][nt][1] * a1;
            pd[mt][0][hs] += acc[mt][nt][0] * d0 + acc[mt][nt][1] * d1;
            ps[mt][1][hs] += acc[mt][nt][2] * a0 + acc[mt][nt][3] * a1;
            pd[mt][1][hs] += acc[mt][nt][2] * d0 + acc[mt][nt][3] * d1;
            int r0 = row0 + wr * 32 + mt * 16 + g4;
            if (r0 < n)
                *(float2*)(g_xw + (size_t)r0 * 128 + col) =
                    make_float2(acc[mt][nt][0], acc[mt][nt][1]);
            if (r0 + 8 < n)
                *(float2*)(g_xw + (size_t)(r0 + 8) * 128 + col) =
                    make_float2(acc[mt][nt][2], acc[mt][nt][3]);
        }
    }
    // Quad reduce (lanes sharing g4)
    #pragma unroll
    for (int mt = 0; mt < 2; mt++)
        #pragma unroll
        for (int rs = 0; rs < 2; rs++)
            #pragma unroll
            for (int hs = 0; hs < 2; hs++) {
                float v = ps[mt][rs][hs];
                v += __shfl_xor_sync(0xffffffffu, v, 1);
                v += __shfl_xor_sync(0xffffffffu, v, 2);
                ps[mt][rs][hs] = v;
                float w = pd[mt][rs][hs];
                w += __shfl_xor_sync(0xffffffffu, w, 1);
                w += __shfl_xor_sync(0xffffffffu, w, 2);
                pd[mt][rs][hs] = w;
            }
    // q=0: ssrc head0, q=1: ssrc head1, q=2: sdst head0, q=3: sdst head1
    {
        int headG = wc * 2 + (q & 1);
        #pragma unroll
        for (int mt = 0; mt < 2; mt++)
            #pragma unroll
            for (int rs = 0; rs < 2; rs++) {
                int r = row0 + wr * 32 + mt * 16 + g4 + rs * 8;
                if (r < n) {
                    float v = (q < 2) ? ps[mt][rs][q & 1] : pd[mt][rs][q & 1];
                    float* dst = (q < 2) ? g_ssrc : g_sdst;
                    dst[(size_t)r * 4 + headG] = v;
                }
            }
    }
}

// ---------------------------------------------------------------------------
// CSR build (once; edge structure identical across layers)
// ---------------------------------------------------------------------------
__global__ void hist_k(const int* __restrict__ ei, int E, int E2)
{
    int e = blockIdx.x * blockDim.x + threadIdx.x;
    if (e >= E2) return;
    int d = (e < E) ? __ldg(ei + E + e) : (e - E);
    atomicAdd(g_counts + d, 1);
}

__global__ __launch_bounds__(1024) void scan_k(int n, int E2)
{
    __shared__ int warpsums[32];
    __shared__ int s_carry;
    int lane = threadIdx.x & 31, wid = threadIdx.x >> 5;
    if (threadIdx.x == 0) s_carry = 0;
    __syncthreads();

    for (int base = 0; base < n; base += 1024) {
        int i = base + threadIdx.x;
        int v = (i < n) ? g_counts[i] : 0;
        int x = v;
        #pragma unroll
        for (int off = 1; off < 32; off <<= 1) {
            int t = __shfl_up_sync(0xffffffffu, x, off);
            if (lane >= off) x += t;
        }
        if (lane == 31) warpsums[wid] = x;
        __syncthreads();
        if (wid == 0) {
            int ws = warpsums[lane];
            #pragma unroll
            for (int off = 1; off < 32; off <<= 1) {
                int t = __shfl_up_sync(0xffffffffu, ws, off);
                if (lane >= off) ws += t;
            }
            warpsums[lane] = ws;
        }
        __syncthreads();
        int incl = x + (wid > 0 ? warpsums[wid - 1] : 0);
        int carry = s_carry;
        if (i < n) {
            g_rowptr[i + 1] = carry + incl;
            g_cursor[i] = carry + incl - v;
        }
        __syncthreads();
        if (threadIdx.x == 1023) s_carry = carry + warpsums[31];
        __syncthreads();
    }
    if (threadIdx.x == 0) { g_rowptr[0] = 0; g_rowptr[n] = E2; }
}

__global__ void scatter_k(const int* __restrict__ ei, int E, int E2)
{
    int e = blockIdx.x * blockDim.x + threadIdx.x;
    if (e >= E2) return;
    int s, d;
    if (e < E) { s = __ldg(ei + e); d = __ldg(ei + E + e); }
    else       { s = d = e - E; }
    int pos = atomicAdd(g_cursor + d, 1);
    g_csr[pos] = s;
}

// ---------------------------------------------------------------------------
// Fused per-destination softmax + aggregation + epilogue. One warp per node.
// (No max subtraction: scores are O(1); exp/sum(exp) is shift-invariant.)
// ---------------------------------------------------------------------------
__global__ __launch_bounds__(256) void fused_gat_k(
    const float* __restrict__ bias, float* __restrict__ out, int n, int mode)
{
    int gid = blockIdx.x * blockDim.x + threadIdx.x;
    int node = gid >> 5, lane = gid & 31;
    if (node >= n) return;

    int beg = g_rowptr[node];
    int end = g_rowptr[node + 1];

    float4 sd = *(const float4*)(g_sdst + (size_t)node * 4);

    float4 den = make_float4(0.f, 0.f, 0.f, 0.f);
    for (int j = beg + lane; j < end; j += 32) {
        int s = g_csr[j];
        float4 ss = *(const float4*)(g_ssrc + (size_t)s * 4);
        float4 a;
        a.x = ss.x + sd.x; a.x = a.x > 0.f ? a.x : 0.2f * a.x;
        a.y = ss.y + sd.y; a.y = a.y > 0.f ? a.y : 0.2f * a.y;
        a.z = ss.z + sd.z; a.z = a.z > 0.f ? a.z : 0.2f * a.z;
        a.w = ss.w + sd.w; a.w = a.w > 0.f ? a.w : 0.2f * a.w;
        float4 ex;
        ex.x = expf(a.x); ex.y = expf(a.y); ex.z = expf(a.z); ex.w = expf(a.w);
        *(float4*)(g_alpha + (size_t)j * 4) = ex;
        den.x += ex.x; den.y += ex.y; den.z += ex.z; den.w += ex.w;
    }
    #pragma unroll
    for (int off = 16; off > 0; off >>= 1) {
        den.x += __shfl_xor_sync(0xffffffffu, den.x, off);
        den.y += __shfl_xor_sync(0xffffffffu, den.y, off);
        den.z += __shfl_xor_sync(0xffffffffu, den.z, off);
        den.w += __shfl_xor_sync(0xffffffffu, den.w, off);
    }

    int h = lane >> 3;
    float den_h = (h == 0) ? den.x : (h == 1) ? den.y : (h == 2) ? den.z : den.w;
    float inv = 1.0f / fmaxf(den_h, 1e-16f);

    float4 acc = make_float4(0.f, 0.f, 0.f, 0.f);
    #pragma unroll 4
    for (int j = beg; j < end; j++) {
        int s = g_csr[j];
        float at = g_alpha[(size_t)j * 4 + h] * inv;
        float4 v = *(const float4*)(g_xw + (size_t)s * 128 + lane * 4);
        acc.x = fmaf(v.x, at, acc.x);
        acc.y = fmaf(v.y, at, acc.y);
        acc.z = fmaf(v.z, at, acc.z);
        acc.w = fmaf(v.w, at, acc.w);
    }

    if (mode == 0) {
        float4 b = *(const float4*)(bias + lane * 4);
        float4 o;
        o.x = acc.x + b.x; o.x = o.x > 0.f ? o.x : (expf(o.x) - 1.f);
        o.y = acc.y + b.y; o.y = o.y > 0.f ? o.y : (expf(o.y) - 1.f);
        o.z = acc.z + b.z; o.z = o.z > 0.f ? o.z : (expf(o.z) - 1.f);
        o.w = acc.w + b.w; o.w = o.w > 0.f ? o.w : (expf(o.w) - 1.f);
        *(float4*)(out + (size_t)node * 128 + lane * 4) = o;
    } else {
        acc.x += __shfl_xor_sync(0xffffffffu, acc.x, 8);
        acc.y += __shfl_xor_sync(0xffffffffu, acc.y, 8);
        acc.z += __shfl_xor_sync(0xffffffffu, acc.z, 8);
        acc.w += __shfl_xor_sync(0xffffffffu, acc.w, 8);
        acc.x += __shfl_xor_sync(0xffffffffu, acc.x, 16);
        acc.y += __shfl_xor_sync(0xffffffffu, acc.y, 16);
        acc.z += __shfl_xor_sync(0xffffffffu, acc.z, 16);
        acc.w += __shfl_xor_sync(0xffffffffu, acc.w, 16);
        if (lane < 8) {
            float4 b = *(const float4*)(bias + lane * 4);
            float4 o;
            o.x = 0.25f * acc.x + b.x;
            o.y = 0.25f * acc.y + b.y;
            o.z = 0.25f * acc.z + b.z;
            o.w = 0.25f * acc.w + b.w;
            *(float4*)(out + (size_t)node * 32 + lane * 4) = o;
        }
    }
}

// ---------------------------------------------------------------------------
extern "C" void kernel_launch(void* const* d_in, const int* in_sizes, int n_in,
                              void* d_out, int out_size)
{
    const float* x  = (const float*)d_in[0];
    const int*   ei = (const int*)d_in[1];
    const float* W[3]  = {(const float*)d_in[2], (const float*)d_in[6],  (const float*)d_in[10]};
    const float* AS[3] = {(const float*)d_in[3], (const float*)d_in[7],  (const float*)d_in[11]};
    const float* AD[3] = {(const float*)d_in[4], (const float*)d_in[8],  (const float*)d_in[12]};
    const float* B[3]  = {(const float*)d_in[5], (const float*)d_in[9],  (const float*)d_in[13]};

    int n  = in_sizes[0] / 128;
    int E  = in_sizes[1] / 2;
    int E2 = E + n;

    float* hbuf = nullptr;
    cudaGetSymbolAddress((void**)&hbuf, g_h);
    int* counts_ptr = nullptr;
    cudaGetSymbolAddress((void**)&counts_ptr, g_counts);
    float* whi = nullptr;
    cudaGetSymbolAddress((void**)&whi, g_Whi32);
    float* wlo = nullptr;
    cudaGetSymbolAddress((void**)&wlo, g_Wlo32);

    const int SMEM_TC = (2 * 64 * 64 + 2 * 128 * 64) * 8;   // 196608 B = 192 KB
    cudaFuncSetAttribute(gemm_tf32_k, cudaFuncAttributeMaxDynamicSharedMemorySize, SMEM_TC);

    // Weight prep + CSR build
    prep_w_k<<<(3 * 16384 + 255) / 256, 256>>>(W[0], W[1], W[2]);
    cudaMemsetAsync(counts_ptr, 0, (size_t)n * sizeof(int));
    hist_k<<<(E2 + 255) / 256, 256>>>(ei, E, E2);
    scan_k<<<1, 1024>>>(n, E2);
    scatter_k<<<(E2 + 255) / 256, 256>>>(ei, E, E2);

    const float* in = x;
    for (int L = 0; L < 3; L++) {
        gemm_tf32_k<<<(n + 63) / 64, 128, SMEM_TC>>>(
            in, whi + L * 16384, wlo + L * 16384, AS[L], AD[L], n);
        if (L < 2) {
            fused_gat_k<<<(n * 32 + 255) / 256, 256>>>(B[L], hbuf, n, 0);
            in = hbuf;
        } else {
            fused_gat_k<<<(n * 32 + 255) / 256, 256>>>(B[2], (float*)d_out, n, 1);
        }
    }
}

// round 5
// speedup vs baseline: 1.0035x; 1.0035x over previous
#include <cuda_runtime.h>
#include <cuda_bf16.h>
#include <math_constants.h>
#include <cstdint>

// Problem constants (reference: N=100000, E=1200000, all dims 128)
#define MAXN 100000
#define MAXE 1200000
#define MAXE2 (MAXE + MAXN)

// Scratch (device globals — allocation-free rule)
__device__ __align__(16) float g_xw[MAXN * 128];
__device__ __align__(16) float g_h[MAXN * 128];
__device__ __align__(16) float g_ssrc[MAXN * 4];
__device__ __align__(16) float g_sdst[MAXN * 4];
__device__ __align__(16) float g_alpha[MAXE2 * 4];

__device__ int g_counts[MAXN];
__device__ int g_cursor[MAXN];
__device__ int g_rowptr[MAXN + 1];
__device__ int g_csr[MAXE2];

// Pre-split weights: tf32 hi/lo (stored as fp32 bit patterns), transposed [n][k]
__device__ __align__(16) float g_Whi32[3 * 128 * 128];
__device__ __align__(16) float g_Wlo32[3 * 128 * 128];

// ---------------------------------------------------------------------------
__device__ __forceinline__ float to_tf32(float x) {
    uint32_t u;
    asm("cvt.rna.tf32.f32 %0, %1;" : "=r"(u) : "f"(x));
    return __uint_as_float(u);
}

__device__ __forceinline__ void mma_tf32(float* c, float2 a_lo, float2 a_hi, float2 b) {
    // a_lo = {a0 (row g,   col q), a2 (row g,   col q+4)}
    // a_hi = {a1 (row g+8, col q), a3 (row g+8, col q+4)}
    // b    = {b0 (k q, n g),       b1 (k q+4, n g)}
    asm("mma.sync.aligned.m16n8k8.row.col.f32.tf32.tf32.f32 "
        "{%0,%1,%2,%3}, {%4,%5,%6,%7}, {%8,%9}, {%0,%1,%2,%3};"
        : "+f"(c[0]), "+f"(c[1]), "+f"(c[2]), "+f"(c[3])
        : "r"(__float_as_uint(a_lo.x)), "r"(__float_as_uint(a_hi.x)),
          "r"(__float_as_uint(a_lo.y)), "r"(__float_as_uint(a_hi.y)),
          "r"(__float_as_uint(b.x)),    "r"(__float_as_uint(b.y)));
}

// Swizzled float2 slot: tile stored as float2[rows][64]; pair slot f holds
// k-columns (8*(f/4) + f%4, +4). Swizzle bits 2..3 of f by (row & 3).
__device__ __forceinline__ int slot_idx(int row, int f) {
    return row * 64 + (f ^ ((row & 3) << 2));
}

// ---------------------------------------------------------------------------
// Weight prep: W[k][n] fp32 -> tf32 hi/lo, transposed to [n][k]
// ---------------------------------------------------------------------------
__global__ void prep_w_k(const float* __restrict__ W0, const float* __restrict__ W1,
                         const float* __restrict__ W2)
{
    int i = blockIdx.x * blockDim.x + threadIdx.x;
    if (i >= 3 * 16384) return;
    int l = i >> 14, r = i & 16383;
    int k = r >> 7, nn = r & 127;
    const float* W = (l == 0) ? W0 : (l == 1) ? W1 : W2;
    float x = W[k * 128 + nn];
    float hi = to_tf32(x);
    g_Whi32[l * 16384 + nn * 128 + k] = hi;
    g_Wlo32[l * 16384 + nn * 128 + k] = to_tf32(x - hi);
}

// ---------------------------------------------------------------------------
// 3xTF32 GEMM: g_xw[64 rows/block, 128] = A @ W, with fused score epilogue
// (g_ssrc/g_sdst). Block: 128 threads (4 warps, each 32 rows x 64 cols).
// Smem: A_hi/A_lo (64x128) + W_hi/W_lo (128x128) = 192 KB, loaded once.
// ---------------------------------------------------------------------------
__global__ __launch_bounds__(128) void gemm_tf32_k(
    const float* __restrict__ A,
    const float* __restrict__ Whi, const float* __restrict__ Wlo,
    const float* __restrict__ as_, const float* __restrict__ ad_, int n)
{
    extern __shared__ float2 sm2[];
    float2* sAhi = sm2;                 // 64*64 float2
    float2* sAlo = sm2 + 64 * 64;
    float2* sWhi = sm2 + 2 * 64 * 64;   // 128*64 float2
    float2* sWlo = sm2 + 2 * 64 * 64 + 128 * 64;

    int tid = threadIdx.x;
    int wid = tid >> 5, lane = tid & 31;
    int row0 = blockIdx.x * 64;

    // Fill W tiles: 128 rows x 16 k-groups, both hi & lo
    #pragma unroll
    for (int it = 0; it < 16; it++) {
        int id = tid + it * 128;            // 0..2047
        int nr = id >> 4, g = id & 15;
        const float4* ph = (const float4*)(Whi + nr * 128 + g * 8);
        const float4* pl = (const float4*)(Wlo + nr * 128 + g * 8);
        float4 h1 = ph[0], h2 = ph[1];
        float4 l1 = pl[0], l2 = pl[1];
        sWhi[slot_idx(nr, 4 * g + 0)] = make_float2(h1.x, h2.x);
        sWhi[slot_idx(nr, 4 * g + 1)] = make_float2(h1.y, h2.y);
        sWhi[slot_idx(nr, 4 * g + 2)] = make_float2(h1.z, h2.z);
        sWhi[slot_idx(nr, 4 * g + 3)] = make_float2(h1.w, h2.w);
        sWlo[slot_idx(nr, 4 * g + 0)] = make_float2(l1.x, l2.x);
        sWlo[slot_idx(nr, 4 * g + 1)] = make_float2(l1.y, l2.y);
        sWlo[slot_idx(nr, 4 * g + 2)] = make_float2(l1.z, l2.z);
        sWlo[slot_idx(nr, 4 * g + 3)] = make_float2(l1.w, l2.w);
    }
    // Fill A tiles with tf32 split: 64 rows x 16 k-groups
    #pragma unroll
    for (int it = 0; it < 8; it++) {
        int id = tid + it * 128;            // 0..1023
        int r = id >> 4, g = id & 15;
        int grow = row0 + r;
        float4 v1 = make_float4(0.f, 0.f, 0.f, 0.f), v2 = v1;
        if (grow < n) {
            const float4* p = (const float4*)(A + (size_t)grow * 128 + g * 8);
            v1 = __ldg(p); v2 = __ldg(p + 1);
        }
        float h[8], l[8];
        float vv[8] = {v1.x, v1.y, v1.z, v1.w, v2.x, v2.y, v2.z, v2.w};
        #pragma unroll
        for (int c = 0; c < 8; c++) {
            h[c] = to_tf32(vv[c]);
            l[c] = to_tf32(vv[c] - h[c]);
        }
        #pragma unroll
        for (int c = 0; c < 4; c++) {
            sAhi[slot_idx(r, 4 * g + c)] = make_float2(h[c], h[c + 4]);
            sAlo[slot_idx(r, 4 * g + c)] = make_float2(l[c], l[c + 4]);
        }
    }
    __syncthreads();

    int q = lane & 3, g4 = lane >> 2;
    int wr = wid >> 1, wc = wid & 1;     // warp: rows wr*32.., cols wc*64..

    float acc[2][8][4];
    #pragma unroll
    for (int mt = 0; mt < 2; mt++)
        #pragma unroll
        for (int nt = 0; nt < 8; nt++)
            #pragma unroll
            for (int i = 0; i < 4; i++) acc[mt][nt][i] = 0.f;

    #pragma unroll
    for (int ks = 0; ks < 16; ks++) {
        int sx = 4 * (ks ^ (g4 & 3)) + q;     // swizzled f (row&3 == g4&3 for all operand rows)
        float2 ah[2][2], al[2][2];
        #pragma unroll
        for (int mt = 0; mt < 2; mt++) {
            int r0 = wr * 32 + mt * 16 + g4;
            ah[mt][0] = sAhi[r0 * 64 + sx];
            ah[mt][1] = sAhi[(r0 + 8) * 64 + sx];
            al[mt][0] = sAlo[r0 * 64 + sx];
            al[mt][1] = sAlo[(r0 + 8) * 64 + sx];
        }
        #pragma unroll
        for (int nt = 0; nt < 8; nt++) {
            int nr = wc * 64 + nt * 8 + g4;
            float2 bh = sWhi[nr * 64 + sx];
            float2 bl = sWlo[nr * 64 + sx];
            #pragma unroll
            for (int mt = 0; mt < 2; mt++) {
                mma_tf32(acc[mt][nt], ah[mt][0], ah[mt][1], bh);   // hi*hi
                mma_tf32(acc[mt][nt], al[mt][0], al[mt][1], bh);   // lo*hi
                mma_tf32(acc[mt][nt], ah[mt][0], ah[mt][1], bl);   // hi*lo
            }
        }
    }

    // Epilogue: write xw (float2, 32B-sector coalesced) + fused attn scores.
    // c layout: c0: (row, col), c1: (row, col+1), c2: (row+8, col), c3: (row+8, col+1)
    // with row = wr*32 + mt*16 + g4, col = wc*64 + nt*8 + q*2.
    float ps[2][2][2] = {}, pd[2][2][2] = {};   // [mt][rowsel][head-in-warp]
    #pragma unroll
    for (int mt = 0; mt < 2; mt++) {
        #pragma unroll
        for (int nt = 0; nt < 8; nt++) {
            int col = wc * 64 + nt * 8 + q * 2;
            float a0 = __ldg(as_ + col), a1 = __ldg(as_ + col + 1);
            float d0 = __ldg(ad_ + col), d1 = __ldg(ad_ + col + 1);
            int hs = nt >> 2;
            ps[mt][0][hs] += acc[mt][nt][0] * a0 + acc[mt][nt][1] * a1;
            pd[mt][0][hs] += acc[mt][nt][0] * d0 + acc[mt][nt][1] * d1;
            ps[mt][1][hs] += acc[mt][nt][2] * a0 + acc[mt][nt][3] * a1;
            pd[mt][1][hs] += acc[mt][nt][2] * d0 + acc[mt][nt][3] * d1;
            int r0 = row0 + wr * 32 + mt * 16 + g4;
            if (r0 < n)
                *(float2*)(g_xw + (size_t)r0 * 128 + col) =
                    make_float2(acc[mt][nt][0], acc[mt][nt][1]);
            if (r0 + 8 < n)
                *(float2*)(g_xw + (size_t)(r0 + 8) * 128 + col) =
                    make_float2(acc[mt][nt][2], acc[mt][nt][3]);
        }
    }
    // Quad reduce (lanes sharing g4)
    #pragma unroll
    for (int mt = 0; mt < 2; mt++)
        #pragma unroll
        for (int rs = 0; rs < 2; rs++)
            #pragma unroll
            for (int hs = 0; hs < 2; hs++) {
                float v = ps[mt][rs][hs];
                v += __shfl_xor_sync(0xffffffffu, v, 1);
                v += __shfl_xor_sync(0xffffffffu, v, 2);
                ps[mt][rs][hs] = v;
                float w = pd[mt][rs][hs];
                w += __shfl_xor_sync(0xffffffffu, w, 1);
                w += __shfl_xor_sync(0xffffffffu, w, 2);
                pd[mt][rs][hs] = w;
            }
    // q=0: ssrc head0, q=1: ssrc head1, q=2: sdst head0, q=3: sdst head1
    {
        int headG = wc * 2 + (q & 1);
        #pragma unroll
        for (int mt = 0; mt < 2; mt++)
            #pragma unroll
            for (int rs = 0; rs < 2; rs++) {
                int r = row0 + wr * 32 + mt * 16 + g4 + rs * 8;
                if (r < n) {
                    float v = (q < 2) ? ps[mt][rs][q & 1] : pd[mt][rs][q & 1];
                    float* dst = (q < 2) ? g_ssrc : g_sdst;
                    dst[(size_t)r * 4 + headG] = v;
                }
            }
    }
}

// ---------------------------------------------------------------------------
// CSR build (once; edge structure identical across layers)
// ---------------------------------------------------------------------------
__global__ void hist_k(const int* __restrict__ ei, int E, int E2)
{
    int e = blockIdx.x * blockDim.x + threadIdx.x;
    if (e >= E2) return;
    int d = (e < E) ? __ldg(ei + E + e) : (e - E);
    atomicAdd(g_counts + d, 1);
}

__global__ __launch_bounds__(1024) void scan_k(int n, int E2)
{
    __shared__ int warpsums[32];
    __shared__ int s_carry;
    int lane = threadIdx.x & 31, wid = threadIdx.x >> 5;
    if (threadIdx.x == 0) s_carry = 0;
    __syncthreads();

    for (int base = 0; base < n; base += 1024) {
        int i = base + threadIdx.x;
        int v = (i < n) ? g_counts[i] : 0;
        int x = v;
        #pragma unroll
        for (int off = 1; off < 32; off <<= 1) {
            int t = __shfl_up_sync(0xffffffffu, x, off);
            if (lane >= off) x += t;
        }
        if (lane == 31) warpsums[wid] = x;
        __syncthreads();
        if (wid == 0) {
            int ws = warpsums[lane];
            #pragma unroll
            for (int off = 1; off < 32; off <<= 1) {
                int t = __shfl_up_sync(0xffffffffu, ws, off);
                if (lane >= off) ws += t;
            }
            warpsums[lane] = ws;
        }
        __syncthreads();
        int incl = x + (wid > 0 ? warpsums[wid - 1] : 0);
        int carry = s_carry;
        if (i < n) {
            g_rowptr[i + 1] = carry + incl;
            g_cursor[i] = carry + incl - v;
        }
        __syncthreads();
        if (threadIdx.x == 1023) s_carry = carry + warpsums[31];
        __syncthreads();
    }
    if (threadIdx.x == 0) { g_rowptr[0] = 0; g_rowptr[n] = E2; }
}

__global__ void scatter_k(const int* __restrict__ ei, int E, int E2)
{
    int e = blockIdx.x * blockDim.x + threadIdx.x;
    if (e >= E2) return;
    int s, d;
    if (e < E) { s = __ldg(ei + e); d = __ldg(ei + E + e); }
    else       { s = d = e - E; }
    int pos = atomicAdd(g_cursor + d, 1);
    g_csr[pos] = s;
}

// ---------------------------------------------------------------------------
// Fused per-destination softmax + aggregation + epilogue. One warp per node.
// (No max subtraction: scores are O(1); exp/sum(exp) is shift-invariant.)
// ---------------------------------------------------------------------------
__global__ __launch_bounds__(256) void fused_gat_k(
    const float* __restrict__ bias, float* __restrict__ out, int n, int mode)
{
    int gid = blockIdx.x * blockDim.x + threadIdx.x;
    int node = gid >> 5, lane = gid & 31;
    if (node >= n) return;

    int beg = g_rowptr[node];
    int end = g_rowptr[node + 1];

    float4 sd = *(const float4*)(g_sdst + (size_t)node * 4);

    float4 den = make_float4(0.f, 0.f, 0.f, 0.f);
    for (int j = beg + lane; j < end; j += 32) {
        int s = g_csr[j];
        float4 ss = *(const float4*)(g_ssrc + (size_t)s * 4);
        float4 a;
        a.x = ss.x + sd.x; a.x = a.x > 0.f ? a.x : 0.2f * a.x;
        a.y = ss.y + sd.y; a.y = a.y > 0.f ? a.y : 0.2f * a.y;
        a.z = ss.z + sd.z; a.z = a.z > 0.f ? a.z : 0.2f * a.z;
        a.w = ss.w + sd.w; a.w = a.w > 0.f ? a.w : 0.2f * a.w;
        float4 ex;
        ex.x = expf(a.x); ex.y = expf(a.y); ex.z = expf(a.z); ex.w = expf(a.w);
        *(float4*)(g_alpha + (size_t)j * 4) = ex;
        den.x += ex.x; den.y += ex.y; den.z += ex.z; den.w += ex.w;
    }
    #pragma unroll
    for (int off = 16; off > 0; off >>= 1) {
        den.x += __shfl_xor_sync(0xffffffffu, den.x, off);
        den.y += __shfl_xor_sync(0xffffffffu, den.y, off);
        den.z += __shfl_xor_sync(0xffffffffu, den.z, off);
        den.w += __shfl_xor_sync(0xffffffffu, den.w, off);
    }

    int h = lane >> 3;
    float den_h = (h == 0) ? den.x : (h == 1) ? den.y : (h == 2) ? den.z : den.w;
    float inv = 1.0f / fmaxf(den_h, 1e-16f);

    float4 acc = make_float4(0.f, 0.f, 0.f, 0.f);
    #pragma unroll 4
    for (int j = beg; j < end; j++) {
        int s = g_csr[j];
        float at = g_alpha[(size_t)j * 4 + h] * inv;
        float4 v = *(const float4*)(g_xw + (size_t)s * 128 + lane * 4);
        acc.x = fmaf(v.x, at, acc.x);
        acc.y = fmaf(v.y, at, acc.y);
        acc.z = fmaf(v.z, at, acc.z);
        acc.w = fmaf(v.w, at, acc.w);
    }

    if (mode == 0) {
        float4 b = *(const float4*)(bias + lane * 4);
        float4 o;
        o.x = acc.x + b.x; o.x = o.x > 0.f ? o.x : (expf(o.x) - 1.f);
        o.y = acc.y + b.y; o.y = o.y > 0.f ? o.y : (expf(o.y) - 1.f);
        o.z = acc.z + b.z; o.z = o.z > 0.f ? o.z : (expf(o.z) - 1.f);
        o.w = acc.w + b.w; o.w = o.w > 0.f ? o.w : (expf(o.w) - 1.f);
        *(float4*)(out + (size_t)node * 128 + lane * 4) = o;
    } else {
        acc.x += __shfl_xor_sync(0xffffffffu, acc.x, 8);
        acc.y += __shfl_xor_sync(0xffffffffu, acc.y, 8);
        acc.z += __shfl_xor_sync(0xffffffffu, acc.z, 8);
        acc.w += __shfl_xor_sync(0xffffffffu, acc.w, 8);
        acc.x += __shfl_xor_sync(0xffffffffu, acc.x, 16);
        acc.y += __shfl_xor_sync(0xffffffffu, acc.y, 16);
        acc.z += __shfl_xor_sync(0xffffffffu, acc.z, 16);
        acc.w += __shfl_xor_sync(0xffffffffu, acc.w, 16);
        if (lane < 8) {
            float4 b = *(const float4*)(bias + lane * 4);
            float4 o;
            o.x = 0.25f * acc.x + b.x;
            o.y = 0.25f * acc.y + b.y;
            o.z = 0.25f * acc.z + b.z;
            o.w = 0.25f * acc.w + b.w;
            *(float4*)(out + (size_t)node * 32 + lane * 4) = o;
        }
    }
}

// ---------------------------------------------------------------------------
extern "C" void kernel_launch(void* const* d_in, const int* in_sizes, int n_in,
                              void* d_out, int out_size)
{
    const float* x  = (const float*)d_in[0];
    const int*   ei = (const int*)d_in[1];
    const float* W[3]  = {(const float*)d_in[2], (const float*)d_in[6],  (const float*)d_in[10]};
    const float* AS[3] = {(const float*)d_in[3], (const float*)d_in[7],  (const float*)d_in[11]};
    const float* AD[3] = {(const float*)d_in[4], (const float*)d_in[8],  (const float*)d_in[12]};
    const float* B[3]  = {(const float*)d_in[5], (const float*)d_in[9],  (const float*)d_in[13]};

    int n  = in_sizes[0] / 128;
    int E  = in_sizes[1] / 2;
    int E2 = E + n;

    float* hbuf = nullptr;
    cudaGetSymbolAddress((void**)&hbuf, g_h);
    int* counts_ptr = nullptr;
    cudaGetSymbolAddress((void**)&counts_ptr, g_counts);
    float* whi = nullptr;
    cudaGetSymbolAddress((void**)&whi, g_Whi32);
    float* wlo = nullptr;
    cudaGetSymbolAddress((void**)&wlo, g_Wlo32);

    const int SMEM_TC = (2 * 64 * 64 + 2 * 128 * 64) * 8;   // 196608 B = 192 KB
    cudaFuncSetAttribute(gemm_tf32_k, cudaFuncAttributeMaxDynamicSharedMemorySize, SMEM_TC);

    // Weight prep + CSR build
    prep_w_k<<<(3 * 16384 + 255) / 256, 256>>>(W[0], W[1], W[2]);
    cudaMemsetAsync(counts_ptr, 0, (size_t)n * sizeof(int));
    hist_k<<<(E2 + 255) / 256, 256>>>(ei, E, E2);
    scan_k<<<1, 1024>>>(n, E2);
    scatter_k<<<(E2 + 255) / 256, 256>>>(ei, E, E2);

    const float* in = x;
    for (int L = 0; L < 3; L++) {
        gemm_tf32_k<<<(n + 63) / 64, 128, SMEM_TC>>>(
            in, whi + L * 16384, wlo + L * 16384, AS[L], AD[L], n);
        if (L < 2) {
            fused_gat_k<<<(n * 32 + 255) / 256, 256>>>(B[L], hbuf, n, 0);
            in = hbuf;
        } else {
            fused_gat_k<<<(n * 32 + 255) / 256, 256>>>(B[2], (float*)d_out, n, 1);
        }
    }
}

// round 6
// speedup vs baseline: 1.0038x; 1.0003x over previous
#include <cuda_runtime.h>
#include <cuda_bf16.h>
#include <math_constants.h>
#include <cstdint>

// Problem constants (reference: N=100000, E=1200000, all dims 128)
#define MAXN 100000
#define MAXE 1200000
#define MAXE2 (MAXE + MAXN)

// Scratch (device globals — allocation-free rule)
__device__ __align__(16) float g_xw[MAXN * 128];
__device__ __align__(16) float g_h[MAXN * 128];
__device__ __align__(16) float g_ssrc[MAXN * 4];
__device__ __align__(16) float g_sdst[MAXN * 4];
__device__ __align__(16) float g_alpha[MAXE2 * 4];

__device__ int g_counts[MAXN];
__device__ int g_cursor[MAXN];
__device__ int g_rowptr[MAXN + 1];
__device__ int g_csr[MAXE2];

// Pre-split weights: tf32 hi/lo (stored as fp32 bit patterns), transposed [n][k]
__device__ __align__(16) float g_Whi32[3 * 128 * 128];
__device__ __align__(16) float g_Wlo32[3 * 128 * 128];

// ---------------------------------------------------------------------------
__device__ __forceinline__ float to_tf32(float x) {
    uint32_t u;
    asm("cvt.rna.tf32.f32 %0, %1;" : "=r"(u) : "f"(x));
    return __uint_as_float(u);
}

__device__ __forceinline__ void mma_tf32(float* c, float2 a_lo, float2 a_hi, float2 b) {
    // a_lo = {a0 (row g,   col q), a2 (row g,   col q+4)}
    // a_hi = {a1 (row g+8, col q), a3 (row g+8, col q+4)}
    // b    = {b0 (k q, n g),       b1 (k q+4, n g)}
    asm("mma.sync.aligned.m16n8k8.row.col.f32.tf32.tf32.f32 "
        "{%0,%1,%2,%3}, {%4,%5,%6,%7}, {%8,%9}, {%0,%1,%2,%3};"
        : "+f"(c[0]), "+f"(c[1]), "+f"(c[2]), "+f"(c[3])
        : "r"(__float_as_uint(a_lo.x)), "r"(__float_as_uint(a_hi.x)),
          "r"(__float_as_uint(a_lo.y)), "r"(__float_as_uint(a_hi.y)),
          "r"(__float_as_uint(b.x)),    "r"(__float_as_uint(b.y)));
}

// Swizzled float2 slot: tile stored as float2[rows][64]; pair slot f holds
// k-columns (8*(f/4) + f%4, +4). Swizzle bits 2..3 of f by (row & 3).
__device__ __forceinline__ int slot_idx(int row, int f) {
    return row * 64 + (f ^ ((row & 3) << 2));
}

// ---------------------------------------------------------------------------
// Weight prep: W[k][n] fp32 -> tf32 hi/lo, transposed to [n][k]
// ---------------------------------------------------------------------------
__global__ void prep_w_k(const float* __restrict__ W0, const float* __restrict__ W1,
                         const float* __restrict__ W2)
{
    int i = blockIdx.x * blockDim.x + threadIdx.x;
    if (i >= 3 * 16384) return;
    int l = i >> 14, r = i & 16383;
    int k = r >> 7, nn = r & 127;
    const float* W = (l == 0) ? W0 : (l == 1) ? W1 : W2;
    float x = W[k * 128 + nn];
    float hi = to_tf32(x);
    g_Whi32[l * 16384 + nn * 128 + k] = hi;
    g_Wlo32[l * 16384 + nn * 128 + k] = to_tf32(x - hi);
}

// ---------------------------------------------------------------------------
// 3xTF32 GEMM: g_xw[64 rows/block, 128] = A @ W, with fused score epilogue
// (g_ssrc/g_sdst). Block: 128 threads (4 warps, each 32 rows x 64 cols).
// Smem: A_hi/A_lo (64x128) + W_hi/W_lo (128x128) = 192 KB, loaded once.
// ---------------------------------------------------------------------------
__global__ __launch_bounds__(128) void gemm_tf32_k(
    const float* __restrict__ A,
    const float* __restrict__ Whi, const float* __restrict__ Wlo,
    const float* __restrict__ as_, const float* __restrict__ ad_, int n)
{
    extern __shared__ float2 sm2[];
    float2* sAhi = sm2;                 // 64*64 float2
    float2* sAlo = sm2 + 64 * 64;
    float2* sWhi = sm2 + 2 * 64 * 64;   // 128*64 float2
    float2* sWlo = sm2 + 2 * 64 * 64 + 128 * 64;

    int tid = threadIdx.x;
    int wid = tid >> 5, lane = tid & 31;
    int row0 = blockIdx.x * 64;

    // Fill W tiles: 128 rows x 16 k-groups, both hi & lo
    #pragma unroll
    for (int it = 0; it < 16; it++) {
        int id = tid + it * 128;            // 0..2047
        int nr = id >> 4, g = id & 15;
        const float4* ph = (const float4*)(Whi + nr * 128 + g * 8);
        const float4* pl = (const float4*)(Wlo + nr * 128 + g * 8);
        float4 h1 = ph[0], h2 = ph[1];
        float4 l1 = pl[0], l2 = pl[1];
        sWhi[slot_idx(nr, 4 * g + 0)] = make_float2(h1.x, h2.x);
        sWhi[slot_idx(nr, 4 * g + 1)] = make_float2(h1.y, h2.y);
        sWhi[slot_idx(nr, 4 * g + 2)] = make_float2(h1.z, h2.z);
        sWhi[slot_idx(nr, 4 * g + 3)] = make_float2(h1.w, h2.w);
        sWlo[slot_idx(nr, 4 * g + 0)] = make_float2(l1.x, l2.x);
        sWlo[slot_idx(nr, 4 * g + 1)] = make_float2(l1.y, l2.y);
        sWlo[slot_idx(nr, 4 * g + 2)] = make_float2(l1.z, l2.z);
        sWlo[slot_idx(nr, 4 * g + 3)] = make_float2(l1.w, l2.w);
    }
    // Fill A tiles with tf32 split: 64 rows x 16 k-groups
    #pragma unroll
    for (int it = 0; it < 8; it++) {
        int id = tid + it * 128;            // 0..1023
        int r = id >> 4, g = id & 15;
        int grow = row0 + r;
        float4 v1 = make_float4(0.f, 0.f, 0.f, 0.f), v2 = v1;
        if (grow < n) {
            const float4* p = (const float4*)(A + (size_t)grow * 128 + g * 8);
            v1 = __ldg(p); v2 = __ldg(p + 1);
        }
        float h[8], l[8];
        float vv[8] = {v1.x, v1.y, v1.z, v1.w, v2.x, v2.y, v2.z, v2.w};
        #pragma unroll
        for (int c = 0; c < 8; c++) {
            h[c] = to_tf32(vv[c]);
            l[c] = to_tf32(vv[c] - h[c]);
        }
        #pragma unroll
        for (int c = 0; c < 4; c++) {
            sAhi[slot_idx(r, 4 * g + c)] = make_float2(h[c], h[c + 4]);
            sAlo[slot_idx(r, 4 * g + c)] = make_float2(l[c], l[c + 4]);
        }
    }
    __syncthreads();

    int q = lane & 3, g4 = lane >> 2;
    int wr = wid >> 1, wc = wid & 1;     // warp: rows wr*32.., cols wc*64..

    float acc[2][8][4];
    #pragma unroll
    for (int mt = 0; mt < 2; mt++)
        #pragma unroll
        for (int nt = 0; nt < 8; nt++)
            #pragma unroll
            for (int i = 0; i < 4; i++) acc[mt][nt][i] = 0.f;

    #pragma unroll
    for (int ks = 0; ks < 16; ks++) {
        int sx = 4 * (ks ^ (g4 & 3)) + q;     // swizzled f (row&3 == g4&3 for all operand rows)
        float2 ah[2][2], al[2][2];
        #pragma unroll
        for (int mt = 0; mt < 2; mt++) {
            int r0 = wr * 32 + mt * 16 + g4;
            ah[mt][0] = sAhi[r0 * 64 + sx];
            ah[mt][1] = sAhi[(r0 + 8) * 64 + sx];
            al[mt][0] = sAlo[r0 * 64 + sx];
            al[mt][1] = sAlo[(r0 + 8) * 64 + sx];
        }
        #pragma unroll
        for (int nt = 0; nt < 8; nt++) {
            int nr = wc * 64 + nt * 8 + g4;
            float2 bh = sWhi[nr * 64 + sx];
            float2 bl = sWlo[nr * 64 + sx];
            #pragma unroll
            for (int mt = 0; mt < 2; mt++) {
                mma_tf32(acc[mt][nt], ah[mt][0], ah[mt][1], bh);   // hi*hi
                mma_tf32(acc[mt][nt], al[mt][0], al[mt][1], bh);   // lo*hi
                mma_tf32(acc[mt][nt], ah[mt][0], ah[mt][1], bl);   // hi*lo
            }
        }
    }

    // Epilogue: write xw (float2, 32B-sector coalesced) + fused attn scores.
    // c layout: c0: (row, col), c1: (row, col+1), c2: (row+8, col), c3: (row+8, col+1)
    // with row = wr*32 + mt*16 + g4, col = wc*64 + nt*8 + q*2.
    float ps[2][2][2] = {}, pd[2][2][2] = {};   // [mt][rowsel][head-in-warp]
    #pragma unroll
    for (int mt = 0; mt < 2; mt++) {
        #pragma unroll
        for (int nt = 0; nt < 8; nt++) {
            int col = wc * 64 + nt * 8 + q * 2;
            float a0 = __ldg(as_ + col), a1 = __ldg(as_ + col + 1);
            float d0 = __ldg(ad_ + col), d1 = __ldg(ad_ + col + 1);
            int hs = nt >> 2;
            ps[mt][0][hs] += acc[mt][nt][0] * a0 + acc[mt][nt][1] * a1;
            pd[mt][0][hs] += acc[mt][nt][0] * d0 + acc[mt][nt][1] * d1;
            ps[mt][1][hs] += acc[mt][nt][2] * a0 + acc[mt][nt][3] * a1;
            pd[mt][1][hs] += acc[mt][nt][2] * d0 + acc[mt][nt][3] * d1;
            int r0 = row0 + wr * 32 + mt * 16 + g4;
            if (r0 < n)
                *(float2*)(g_xw + (size_t)r0 * 128 + col) =
                    make_float2(acc[mt][nt][0], acc[mt][nt][1]);
            if (r0 + 8 < n)
                *(float2*)(g_xw + (size_t)(r0 + 8) * 128 + col) =
                    make_float2(acc[mt][nt][2], acc[mt][nt][3]);
        }
    }
    // Quad reduce (lanes sharing g4)
    #pragma unroll
    for (int mt = 0; mt < 2; mt++)
        #pragma unroll
        for (int rs = 0; rs < 2; rs++)
            #pragma unroll
            for (int hs = 0; hs < 2; hs++) {
                float v = ps[mt][rs][hs];
                v += __shfl_xor_sync(0xffffffffu, v, 1);
                v += __shfl_xor_sync(0xffffffffu, v, 2);
                ps[mt][rs][hs] = v;
                float w = pd[mt][rs][hs];
                w += __shfl_xor_sync(0xffffffffu, w, 1);
                w += __shfl_xor_sync(0xffffffffu, w, 2);
                pd[mt][rs][hs] = w;
            }
    // q=0: ssrc head0, q=1: ssrc head1, q=2: sdst head0, q=3: sdst head1
    {
        int headG = wc * 2 + (q & 1);
        #pragma unroll
        for (int mt = 0; mt < 2; mt++)
            #pragma unroll
            for (int rs = 0; rs < 2; rs++) {
                int r = row0 + wr * 32 + mt * 16 + g4 + rs * 8;
                if (r < n) {
                    float v = (q < 2) ? ps[mt][rs][q & 1] : pd[mt][rs][q & 1];
                    float* dst = (q < 2) ? g_ssrc : g_sdst;
                    dst[(size_t)r * 4 + headG] = v;
                }
            }
    }
}

// ---------------------------------------------------------------------------
// CSR build (once; edge structure identical across layers)
// ---------------------------------------------------------------------------
__global__ void hist_k(const int* __restrict__ ei, int E, int E2)
{
    int e = blockIdx.x * blockDim.x + threadIdx.x;
    if (e >= E2) return;
    int d = (e < E) ? __ldg(ei + E + e) : (e - E);
    atomicAdd(g_counts + d, 1);
}

__global__ __launch_bounds__(1024) void scan_k(int n, int E2)
{
    __shared__ int warpsums[32];
    __shared__ int s_carry;
    int lane = threadIdx.x & 31, wid = threadIdx.x >> 5;
    if (threadIdx.x == 0) s_carry = 0;
    __syncthreads();

    for (int base = 0; base < n; base += 1024) {
        int i = base + threadIdx.x;
        int v = (i < n) ? g_counts[i] : 0;
        int x = v;
        #pragma unroll
        for (int off = 1; off < 32; off <<= 1) {
            int t = __shfl_up_sync(0xffffffffu, x, off);
            if (lane >= off) x += t;
        }
        if (lane == 31) warpsums[wid] = x;
        __syncthreads();
        if (wid == 0) {
            int ws = warpsums[lane];
            #pragma unroll
            for (int off = 1; off < 32; off <<= 1) {
                int t = __shfl_up_sync(0xffffffffu, ws, off);
                if (lane >= off) ws += t;
            }
            warpsums[lane] = ws;
        }
        __syncthreads();
        int incl = x + (wid > 0 ? warpsums[wid - 1] : 0);
        int carry = s_carry;
        if (i < n) {
            g_rowptr[i + 1] = carry + incl;
            g_cursor[i] = carry + incl - v;
        }
        __syncthreads();
        if (threadIdx.x == 1023) s_carry = carry + warpsums[31];
        __syncthreads();
    }
    if (threadIdx.x == 0) { g_rowptr[0] = 0; g_rowptr[n] = E2; }
}

__global__ void scatter_k(const int* __restrict__ ei, int E, int E2)
{
    int e = blockIdx.x * blockDim.x + threadIdx.x;
    if (e >= E2) return;
    int s, d;
    if (e < E) { s = __ldg(ei + e); d = __ldg(ei + E + e); }
    else       { s = d = e - E; }
    int pos = atomicAdd(g_cursor + d, 1);
    g_csr[pos] = s;
}

// ---------------------------------------------------------------------------
// Fused per-destination softmax + aggregation + epilogue. One warp per node.
// (No max subtraction: scores are O(1); exp/sum(exp) is shift-invariant.)
// ---------------------------------------------------------------------------
__global__ __launch_bounds__(256) void fused_gat_k(
    const float* __restrict__ bias, float* __restrict__ out, int n, int mode)
{
    int gid = blockIdx.x * blockDim.x + threadIdx.x;
    int node = gid >> 5, lane = gid & 31;
    if (node >= n) return;

    int beg = g_rowptr[node];
    int end = g_rowptr[node + 1];

    float4 sd = *(const float4*)(g_sdst + (size_t)node * 4);

    float4 den = make_float4(0.f, 0.f, 0.f, 0.f);
    for (int j = beg + lane; j < end; j += 32) {
        int s = g_csr[j];
        float4 ss = *(const float4*)(g_ssrc + (size_t)s * 4);
        float4 a;
        a.x = ss.x + sd.x; a.x = a.x > 0.f ? a.x : 0.2f * a.x;
        a.y = ss.y + sd.y; a.y = a.y > 0.f ? a.y : 0.2f * a.y;
        a.z = ss.z + sd.z; a.z = a.z > 0.f ? a.z : 0.2f * a.z;
        a.w = ss.w + sd.w; a.w = a.w > 0.f ? a.w : 0.2f * a.w;
        float4 ex;
        ex.x = expf(a.x); ex.y = expf(a.y); ex.z = expf(a.z); ex.w = expf(a.w);
        *(float4*)(g_alpha + (size_t)j * 4) = ex;
        den.x += ex.x; den.y += ex.y; den.z += ex.z; den.w += ex.w;
    }
    #pragma unroll
    for (int off = 16; off > 0; off >>= 1) {
        den.x += __shfl_xor_sync(0xffffffffu, den.x, off);
        den.y += __shfl_xor_sync(0xffffffffu, den.y, off);
        den.z += __shfl_xor_sync(0xffffffffu, den.z, off);
        den.w += __shfl_xor_sync(0xffffffffu, den.w, off);
    }

    int h = lane >> 3;
    float den_h = (h == 0) ? den.x : (h == 1) ? den.y : (h == 2) ? den.z : den.w;
    float inv = 1.0f / fmaxf(den_h, 1e-16f);

    float4 acc = make_float4(0.f, 0.f, 0.f, 0.f);
    #pragma unroll 4
    for (int j = beg; j < end; j++) {
        int s = g_csr[j];
        float at = g_alpha[(size_t)j * 4 + h] * inv;
        float4 v = *(const float4*)(g_xw + (size_t)s * 128 + lane * 4);
        acc.x = fmaf(v.x, at, acc.x);
        acc.y = fmaf(v.y, at, acc.y);
        acc.z = fmaf(v.z, at, acc.z);
        acc.w = fmaf(v.w, at, acc.w);
    }

    if (mode == 0) {
        float4 b = *(const float4*)(bias + lane * 4);
        float4 o;
        o.x = acc.x + b.x; o.x = o.x > 0.f ? o.x : (expf(o.x) - 1.f);
        o.y = acc.y + b.y; o.y = o.y > 0.f ? o.y : (expf(o.y) - 1.f);
        o.z = acc.z + b.z; o.z = o.z > 0.f ? o.z : (expf(o.z) - 1.f);
        o.w = acc.w + b.w; o.w = o.w > 0.f ? o.w : (expf(o.w) - 1.f);
        *(float4*)(out + (size_t)node * 128 + lane * 4) = o;
    } else {
        acc.x += __shfl_xor_sync(0xffffffffu, acc.x, 8);
        acc.y += __shfl_xor_sync(0xffffffffu, acc.y, 8);
        acc.z += __shfl_xor_sync(0xffffffffu, acc.z, 8);
        acc.w += __shfl_xor_sync(0xffffffffu, acc.w, 8);
        acc.x += __shfl_xor_sync(0xffffffffu, acc.x, 16);
        acc.y += __shfl_xor_sync(0xffffffffu, acc.y, 16);
        acc.z += __shfl_xor_sync(0xffffffffu, acc.z, 16);
        acc.w += __shfl_xor_sync(0xffffffffu, acc.w, 16);
        if (lane < 8) {
            float4 b = *(const float4*)(bias + lane * 4);
            float4 o;
            o.x = 0.25f * acc.x + b.x;
            o.y = 0.25f * acc.y + b.y;
            o.z = 0.25f * acc.z + b.z;
            o.w = 0.25f * acc.w + b.w;
            *(float4*)(out + (size_t)node * 32 + lane * 4) = o;
        }
    }
}

// ---------------------------------------------------------------------------
extern "C" void kernel_launch(void* const* d_in, const int* in_sizes, int n_in,
                              void* d_out, int out_size)
{
    const float* x  = (const float*)d_in[0];
    const int*   ei = (const int*)d_in[1];
    const float* W[3]  = {(const float*)d_in[2], (const float*)d_in[6],  (const float*)d_in[10]};
    const float* AS[3] = {(const float*)d_in[3], (const float*)d_in[7],  (const float*)d_in[11]};
    const float* AD[3] = {(const float*)d_in[4], (const float*)d_in[8],  (const float*)d_in[12]};
    const float* B[3]  = {(const float*)d_in[5], (const float*)d_in[9],  (const float*)d_in[13]};

    int n  = in_sizes[0] / 128;
    int E  = in_sizes[1] / 2;
    int E2 = E + n;

    float* hbuf = nullptr;
    cudaGetSymbolAddress((void**)&hbuf, g_h);
    int* counts_ptr = nullptr;
    cudaGetSymbolAddress((void**)&counts_ptr, g_counts);
    float* whi = nullptr;
    cudaGetSymbolAddress((void**)&whi, g_Whi32);
    float* wlo = nullptr;
    cudaGetSymbolAddress((void**)&wlo, g_Wlo32);

    const int SMEM_TC = (2 * 64 * 64 + 2 * 128 * 64) * 8;   // 196608 B = 192 KB
    cudaFuncSetAttribute(gemm_tf32_k, cudaFuncAttributeMaxDynamicSharedMemorySize, SMEM_TC);

    // Weight prep + CSR build
    prep_w_k<<<(3 * 16384 + 255) / 256, 256>>>(W[0], W[1], W[2]);
    cudaMemsetAsync(counts_ptr, 0, (size_t)n * sizeof(int));
    hist_k<<<(E2 + 255) / 256, 256>>>(ei, E, E2);
    scan_k<<<1, 1024>>>(n, E2);
    scatter_k<<<(E2 + 255) / 256, 256>>>(ei, E, E2);

    const float* in = x;
    for (int L = 0; L < 3; L++) {
        gemm_tf32_k<<<(n + 63) / 64, 128, SMEM_TC>>>(
            in, whi + L * 16384, wlo + L * 16384, AS[L], AD[L], n);
        if (L < 2) {
            fused_gat_k<<<(n * 32 + 255) / 256, 256>>>(B[L], hbuf, n, 0);
            in = hbuf;
        } else {
            fused_gat_k<<<(n * 32 + 255) / 256, 256>>>(B[2], (float*)d_out, n, 1);
        }
    }
}

// round 7
// speedup vs baseline: 1.0040x; 1.0002x over previous
#include <cuda_runtime.h>
#include <cuda_bf16.h>
#include <math_constants.h>
#include <cstdint>

// Problem constants (reference: N=100000, E=1200000, all dims 128)
#define MAXN 100000
#define MAXE 1200000
#define MAXE2 (MAXE + MAXN)

// Scratch (device globals — allocation-free rule)
__device__ __align__(16) float g_xw[MAXN * 128];
__device__ __align__(16) float g_h[MAXN * 128];
__device__ __align__(16) float g_ssrc[MAXN * 4];
__device__ __align__(16) float g_sdst[MAXN * 4];
__device__ __align__(16) float g_alpha[MAXE2 * 4];

__device__ int g_counts[MAXN];
__device__ int g_cursor[MAXN];
__device__ int g_rowptr[MAXN + 1];
__device__ int g_csr[MAXE2];

// Pre-split weights: tf32 hi/lo (stored as fp32 bit patterns), transposed [n][k]
__device__ __align__(16) float g_Whi32[3 * 128 * 128];
__device__ __align__(16) float g_Wlo32[3 * 128 * 128];

// ---------------------------------------------------------------------------
__device__ __forceinline__ float to_tf32(float x) {
    uint32_t u;
    asm("cvt.rna.tf32.f32 %0, %1;" : "=r"(u) : "f"(x));
    return __uint_as_float(u);
}

__device__ __forceinline__ void mma_tf32(float* c, float2 a_lo, float2 a_hi, float2 b) {
    // a_lo = {a0 (row g,   col q), a2 (row g,   col q+4)}
    // a_hi = {a1 (row g+8, col q), a3 (row g+8, col q+4)}
    // b    = {b0 (k q, n g),       b1 (k q+4, n g)}
    asm("mma.sync.aligned.m16n8k8.row.col.f32.tf32.tf32.f32 "
        "{%0,%1,%2,%3}, {%4,%5,%6,%7}, {%8,%9}, {%0,%1,%2,%3};"
        : "+f"(c[0]), "+f"(c[1]), "+f"(c[2]), "+f"(c[3])
        : "r"(__float_as_uint(a_lo.x)), "r"(__float_as_uint(a_hi.x)),
          "r"(__float_as_uint(a_lo.y)), "r"(__float_as_uint(a_hi.y)),
          "r"(__float_as_uint(b.x)),    "r"(__float_as_uint(b.y)));
}

// Swizzled float2 slot: tile stored as float2[rows][64]; pair slot f holds
// k-columns (8*(f/4) + f%4, +4). Swizzle bits 2..3 of f by (row & 3).
__device__ __forceinline__ int slot_idx(int row, int f) {
    return row * 64 + (f ^ ((row & 3) << 2));
}

// ---------------------------------------------------------------------------
// Weight prep: W[k][n] fp32 -> tf32 hi/lo, transposed to [n][k]
// ---------------------------------------------------------------------------
__global__ void prep_w_k(const float* __restrict__ W0, const float* __restrict__ W1,
                         const float* __restrict__ W2)
{
    int i = blockIdx.x * blockDim.x + threadIdx.x;
    if (i >= 3 * 16384) return;
    int l = i >> 14, r = i & 16383;
    int k = r >> 7, nn = r & 127;
    const float* W = (l == 0) ? W0 : (l == 1) ? W1 : W2;
    float x = W[k * 128 + nn];
    float hi = to_tf32(x);
    g_Whi32[l * 16384 + nn * 128 + k] = hi;
    g_Wlo32[l * 16384 + nn * 128 + k] = to_tf32(x - hi);
}

// ---------------------------------------------------------------------------
// 3xTF32 GEMM: g_xw[64 rows/block, 128] = A @ W, with fused score epilogue
// (g_ssrc/g_sdst). Block: 128 threads (4 warps, each 32 rows x 64 cols).
// Smem: A_hi/A_lo (64x128) + W_hi/W_lo (128x128) = 192 KB, loaded once.
// ---------------------------------------------------------------------------
__global__ __launch_bounds__(128) void gemm_tf32_k(
    const float* __restrict__ A,
    const float* __restrict__ Whi, const float* __restrict__ Wlo,
    const float* __restrict__ as_, const float* __restrict__ ad_, int n)
{
    extern __shared__ float2 sm2[];
    float2* sAhi = sm2;                 // 64*64 float2
    float2* sAlo = sm2 + 64 * 64;
    float2* sWhi = sm2 + 2 * 64 * 64;   // 128*64 float2
    float2* sWlo = sm2 + 2 * 64 * 64 + 128 * 64;

    int tid = threadIdx.x;
    int wid = tid >> 5, lane = tid & 31;
    int row0 = blockIdx.x * 64;

    // Fill W tiles: 128 rows x 16 k-groups, both hi & lo
    #pragma unroll
    for (int it = 0; it < 16; it++) {
        int id = tid + it * 128;            // 0..2047
        int nr = id >> 4, g = id & 15;
        const float4* ph = (const float4*)(Whi + nr * 128 + g * 8);
        const float4* pl = (const float4*)(Wlo + nr * 128 + g * 8);
        float4 h1 = ph[0], h2 = ph[1];
        float4 l1 = pl[0], l2 = pl[1];
        sWhi[slot_idx(nr, 4 * g + 0)] = make_float2(h1.x, h2.x);
        sWhi[slot_idx(nr, 4 * g + 1)] = make_float2(h1.y, h2.y);
        sWhi[slot_idx(nr, 4 * g + 2)] = make_float2(h1.z, h2.z);
        sWhi[slot_idx(nr, 4 * g + 3)] = make_float2(h1.w, h2.w);
        sWlo[slot_idx(nr, 4 * g + 0)] = make_float2(l1.x, l2.x);
        sWlo[slot_idx(nr, 4 * g + 1)] = make_float2(l1.y, l2.y);
        sWlo[slot_idx(nr, 4 * g + 2)] = make_float2(l1.z, l2.z);
        sWlo[slot_idx(nr, 4 * g + 3)] = make_float2(l1.w, l2.w);
    }
    // Fill A tiles with tf32 split: 64 rows x 16 k-groups
    #pragma unroll
    for (int it = 0; it < 8; it++) {
        int id = tid + it * 128;            // 0..1023
        int r = id >> 4, g = id & 15;
        int grow = row0 + r;
        float4 v1 = make_float4(0.f, 0.f, 0.f, 0.f), v2 = v1;
        if (grow < n) {
            const float4* p = (const float4*)(A + (size_t)grow * 128 + g * 8);
            v1 = __ldg(p); v2 = __ldg(p + 1);
        }
        float h[8], l[8];
        float vv[8] = {v1.x, v1.y, v1.z, v1.w, v2.x, v2.y, v2.z, v2.w};
        #pragma unroll
        for (int c = 0; c < 8; c++) {
            h[c] = to_tf32(vv[c]);
            l[c] = to_tf32(vv[c] - h[c]);
        }
        #pragma unroll
        for (int c = 0; c < 4; c++) {
            sAhi[slot_idx(r, 4 * g + c)] = make_float2(h[c], h[c + 4]);
            sAlo[slot_idx(r, 4 * g + c)] = make_float2(l[c], l[c + 4]);
        }
    }
    __syncthreads();

    int q = lane & 3, g4 = lane >> 2;
    int wr = wid >> 1, wc = wid & 1;     // warp: rows wr*32.., cols wc*64..

    float acc[2][8][4];
    #pragma unroll
    for (int mt = 0; mt < 2; mt++)
        #pragma unroll
        for (int nt = 0; nt < 8; nt++)
            #pragma unroll
            for (int i = 0; i < 4; i++) acc[mt][nt][i] = 0.f;

    #pragma unroll
    for (int ks = 0; ks < 16; ks++) {
        int sx = 4 * (ks ^ (g4 & 3)) + q;     // swizzled f (row&3 == g4&3 for all operand rows)
        float2 ah[2][2], al[2][2];
        #pragma unroll
        for (int mt = 0; mt < 2; mt++) {
            int r0 = wr * 32 + mt * 16 + g4;
            ah[mt][0] = sAhi[r0 * 64 + sx];
            ah[mt][1] = sAhi[(r0 + 8) * 64 + sx];
            al[mt][0] = sAlo[r0 * 64 + sx];
            al[mt][1] = sAlo[(r0 + 8) * 64 + sx];
        }
        #pragma unroll
        for (int nt = 0; nt < 8; nt++) {
            int nr = wc * 64 + nt * 8 + g4;
            float2 bh = sWhi[nr * 64 + sx];
            float2 bl = sWlo[nr * 64 + sx];
            #pragma unroll
            for (int mt = 0; mt < 2; mt++) {
                mma_tf32(acc[mt][nt], ah[mt][0], ah[mt][1], bh);   // hi*hi
                mma_tf32(acc[mt][nt], al[mt][0], al[mt][1], bh);   // lo*hi
                mma_tf32(acc[mt][nt], ah[mt][0], ah[mt][1], bl);   // hi*lo
            }
        }
    }

    // Epilogue: write xw (float2, 32B-sector coalesced) + fused attn scores.
    // c layout: c0: (row, col), c1: (row, col+1), c2: (row+8, col), c3: (row+8, col+1)
    // with row = wr*32 + mt*16 + g4, col = wc*64 + nt*8 + q*2.
    float ps[2][2][2] = {}, pd[2][2][2] = {};   // [mt][rowsel][head-in-warp]
    #pragma unroll
    for (int mt = 0; mt < 2; mt++) {
        #pragma unroll
        for (int nt = 0; nt < 8; nt++) {
            int col = wc * 64 + nt * 8 + q * 2;
            float a0 = __ldg(as_ + col), a1 = __ldg(as_ + col + 1);
            float d0 = __ldg(ad_ + col), d1 = __ldg(ad_ + col + 1);
            int hs = nt >> 2;
            ps[mt][0][hs] += acc[mt][nt][0] * a0 + acc[mt][nt][1] * a1;
            pd[mt][0][hs] += acc[mt][nt][0] * d0 + acc[mt][nt][1] * d1;
            ps[mt][1][hs] += acc[mt][nt][2] * a0 + acc[mt][nt][3] * a1;
            pd[mt][1][hs] += acc[mt][nt][2] * d0 + acc[mt][nt][3] * d1;
            int r0 = row0 + wr * 32 + mt * 16 + g4;
            if (r0 < n)
                *(float2*)(g_xw + (size_t)r0 * 128 + col) =
                    make_float2(acc[mt][nt][0], acc[mt][nt][1]);
            if (r0 + 8 < n)
                *(float2*)(g_xw + (size_t)(r0 + 8) * 128 + col) =
                    make_float2(acc[mt][nt][2], acc[mt][nt][3]);
        }
    }
    // Quad reduce (lanes sharing g4)
    #pragma unroll
    for (int mt = 0; mt < 2; mt++)
        #pragma unroll
        for (int rs = 0; rs < 2; rs++)
            #pragma unroll
            for (int hs = 0; hs < 2; hs++) {
                float v = ps[mt][rs][hs];
                v += __shfl_xor_sync(0xffffffffu, v, 1);
                v += __shfl_xor_sync(0xffffffffu, v, 2);
                ps[mt][rs][hs] = v;
                float w = pd[mt][rs][hs];
                w += __shfl_xor_sync(0xffffffffu, w, 1);
                w += __shfl_xor_sync(0xffffffffu, w, 2);
                pd[mt][rs][hs] = w;
            }
    // q=0: ssrc head0, q=1: ssrc head1, q=2: sdst head0, q=3: sdst head1
    {
        int headG = wc * 2 + (q & 1);
        #pragma unroll
        for (int mt = 0; mt < 2; mt++)
            #pragma unroll
            for (int rs = 0; rs < 2; rs++) {
                int r = row0 + wr * 32 + mt * 16 + g4 + rs * 8;
                if (r < n) {
                    float v = (q < 2) ? ps[mt][rs][q & 1] : pd[mt][rs][q & 1];
                    float* dst = (q < 2) ? g_ssrc : g_sdst;
                    dst[(size_t)r * 4 + headG] = v;
                }
            }
    }
}

// ---------------------------------------------------------------------------
// CSR build (once; edge structure identical across layers)
// ---------------------------------------------------------------------------
__global__ void hist_k(const int* __restrict__ ei, int E, int E2)
{
    int e = blockIdx.x * blockDim.x + threadIdx.x;
    if (e >= E2) return;
    int d = (e < E) ? __ldg(ei + E + e) : (e - E);
    atomicAdd(g_counts + d, 1);
}

__global__ __launch_bounds__(1024) void scan_k(int n, int E2)
{
    __shared__ int warpsums[32];
    __shared__ int s_carry;
    int lane = threadIdx.x & 31, wid = threadIdx.x >> 5;
    if (threadIdx.x == 0) s_carry = 0;
    __syncthreads();

    for (int base = 0; base < n; base += 1024) {
        int i = base + threadIdx.x;
        int v = (i < n) ? g_counts[i] : 0;
        int x = v;
        #pragma unroll
        for (int off = 1; off < 32; off <<= 1) {
            int t = __shfl_up_sync(0xffffffffu, x, off);
            if (lane >= off) x += t;
        }
        if (lane == 31) warpsums[wid] = x;
        __syncthreads();
        if (wid == 0) {
            int ws = warpsums[lane];
            #pragma unroll
            for (int off = 1; off < 32; off <<= 1) {
                int t = __shfl_up_sync(0xffffffffu, ws, off);
                if (lane >= off) ws += t;
            }
            warpsums[lane] = ws;
        }
        __syncthreads();
        int incl = x + (wid > 0 ? warpsums[wid - 1] : 0);
        int carry = s_carry;
        if (i < n) {
            g_rowptr[i + 1] = carry + incl;
            g_cursor[i] = carry + incl - v;
        }
        __syncthreads();
        if (threadIdx.x == 1023) s_carry = carry + warpsums[31];
        __syncthreads();
    }
    if (threadIdx.x == 0) { g_rowptr[0] = 0; g_rowptr[n] = E2; }
}

__global__ void scatter_k(const int* __restrict__ ei, int E, int E2)
{
    int e = blockIdx.x * blockDim.x + threadIdx.x;
    if (e >= E2) return;
    int s, d;
    if (e < E) { s = __ldg(ei + e); d = __ldg(ei + E + e); }
    else       { s = d = e - E; }
    int pos = atomicAdd(g_cursor + d, 1);
    g_csr[pos] = s;
}

// ---------------------------------------------------------------------------
// Fused per-destination softmax + aggregation + epilogue. One warp per node.
// (No max subtraction: scores are O(1); exp/sum(exp) is shift-invariant.)
// ---------------------------------------------------------------------------
__global__ __launch_bounds__(256) void fused_gat_k(
    const float* __restrict__ bias, float* __restrict__ out, int n, int mode)
{
    int gid = blockIdx.x * blockDim.x + threadIdx.x;
    int node = gid >> 5, lane = gid & 31;
    if (node >= n) return;

    int beg = g_rowptr[node];
    int end = g_rowptr[node + 1];

    float4 sd = *(const float4*)(g_sdst + (size_t)node * 4);

    float4 den = make_float4(0.f, 0.f, 0.f, 0.f);
    for (int j = beg + lane; j < end; j += 32) {
        int s = g_csr[j];
        float4 ss = *(const float4*)(g_ssrc + (size_t)s * 4);
        float4 a;
        a.x = ss.x + sd.x; a.x = a.x > 0.f ? a.x : 0.2f * a.x;
        a.y = ss.y + sd.y; a.y = a.y > 0.f ? a.y : 0.2f * a.y;
        a.z = ss.z + sd.z; a.z = a.z > 0.f ? a.z : 0.2f * a.z;
        a.w = ss.w + sd.w; a.w = a.w > 0.f ? a.w : 0.2f * a.w;
        float4 ex;
        ex.x = expf(a.x); ex.y = expf(a.y); ex.z = expf(a.z); ex.w = expf(a.w);
        *(float4*)(g_alpha + (size_t)j * 4) = ex;
        den.x += ex.x; den.y += ex.y; den.z += ex.z; den.w += ex.w;
    }
    #pragma unroll
    for (int off = 16; off > 0; off >>= 1) {
        den.x += __shfl_xor_sync(0xffffffffu, den.x, off);
        den.y += __shfl_xor_sync(0xffffffffu, den.y, off);
        den.z += __shfl_xor_sync(0xffffffffu, den.z, off);
        den.w += __shfl_xor_sync(0xffffffffu, den.w, off);
    }

    int h = lane >> 3;
    float den_h = (h == 0) ? den.x : (h == 1) ? den.y : (h == 2) ? den.z : den.w;
    float inv = 1.0f / fmaxf(den_h, 1e-16f);

    float4 acc = make_float4(0.f, 0.f, 0.f, 0.f);
    #pragma unroll 4
    for (int j = beg; j < end; j++) {
        int s = g_csr[j];
        float at = g_alpha[(size_t)j * 4 + h] * inv;
        float4 v = *(const float4*)(g_xw + (size_t)s * 128 + lane * 4);
        acc.x = fmaf(v.x, at, acc.x);
        acc.y = fmaf(v.y, at, acc.y);
        acc.z = fmaf(v.z, at, acc.z);
        acc.w = fmaf(v.w, at, acc.w);
    }

    if (mode == 0) {
        float4 b = *(const float4*)(bias + lane * 4);
        float4 o;
        o.x = acc.x + b.x; o.x = o.x > 0.f ? o.x : (expf(o.x) - 1.f);
        o.y = acc.y + b.y; o.y = o.y > 0.f ? o.y : (expf(o.y) - 1.f);
        o.z = acc.z + b.z; o.z = o.z > 0.f ? o.z : (expf(o.z) - 1.f);
        o.w = acc.w + b.w; o.w = o.w > 0.f ? o.w : (expf(o.w) - 1.f);
        *(float4*)(out + (size_t)node * 128 + lane * 4) = o;
    } else {
        acc.x += __shfl_xor_sync(0xffffffffu, acc.x, 8);
        acc.y += __shfl_xor_sync(0xffffffffu, acc.y, 8);
        acc.z += __shfl_xor_sync(0xffffffffu, acc.z, 8);
        acc.w += __shfl_xor_sync(0xffffffffu, acc.w, 8);
        acc.x += __shfl_xor_sync(0xffffffffu, acc.x, 16);
        acc.y += __shfl_xor_sync(0xffffffffu, acc.y, 16);
        acc.z += __shfl_xor_sync(0xffffffffu, acc.z, 16);
        acc.w += __shfl_xor_sync(0xffffffffu, acc.w, 16);
        if (lane < 8) {
            float4 b = *(const float4*)(bias + lane * 4);
            float4 o;
            o.x = 0.25f * acc.x + b.x;
            o.y = 0.25f * acc.y + b.y;
            o.z = 0.25f * acc.z + b.z;
            o.w = 0.25f * acc.w + b.w;
            *(float4*)(out + (size_t)node * 32 + lane * 4) = o;
        }
    }
}

// ---------------------------------------------------------------------------
extern "C" void kernel_launch(void* const* d_in, const int* in_sizes, int n_in,
                              void* d_out, int out_size)
{
    const float* x  = (const float*)d_in[0];
    const int*   ei = (const int*)d_in[1];
    const float* W[3]  = {(const float*)d_in[2], (const float*)d_in[6],  (const float*)d_in[10]};
    const float* AS[3] = {(const float*)d_in[3], (const float*)d_in[7],  (const float*)d_in[11]};
    const float* AD[3] = {(const float*)d_in[4], (const float*)d_in[8],  (const float*)d_in[12]};
    const float* B[3]  = {(const float*)d_in[5], (const float*)d_in[9],  (const float*)d_in[13]};

    int n  = in_sizes[0] / 128;
    int E  = in_sizes[1] / 2;
    int E2 = E + n;

    float* hbuf = nullptr;
    cudaGetSymbolAddress((void**)&hbuf, g_h);
    int* counts_ptr = nullptr;
    cudaGetSymbolAddress((void**)&counts_ptr, g_counts);
    float* whi = nullptr;
    cudaGetSymbolAddress((void**)&whi, g_Whi32);
    float* wlo = nullptr;
    cudaGetSymbolAddress((void**)&wlo, g_Wlo32);

    const int SMEM_TC = (2 * 64 * 64 + 2 * 128 * 64) * 8;   // 196608 B = 192 KB
    cudaFuncSetAttribute(gemm_tf32_k, cudaFuncAttributeMaxDynamicSharedMemorySize, SMEM_TC);

    // Weight prep + CSR build
    prep_w_k<<<(3 * 16384 + 255) / 256, 256>>>(W[0], W[1], W[2]);
    cudaMemsetAsync(counts_ptr, 0, (size_t)n * sizeof(int));
    hist_k<<<(E2 + 255) / 256, 256>>>(ei, E, E2);
    scan_k<<<1, 1024>>>(n, E2);
    scatter_k<<<(E2 + 255) / 256, 256>>>(ei, E, E2);

    const float* in = x;
    for (int L = 0; L < 3; L++) {
        gemm_tf32_k<<<(n + 63) / 64, 128, SMEM_TC>>>(
            in, whi + L * 16384, wlo + L * 16384, AS[L], AD[L], n);
        if (L < 2) {
            fused_gat_k<<<(n * 32 + 255) / 256, 256>>>(B[L], hbuf, n, 0);
            in = hbuf;
        } else {
            fused_gat_k<<<(n * 32 + 255) / 256, 256>>>(B[2], (float*)d_out, n, 1);
        }
    }
}

// round 8
// speedup vs baseline: 1.0062x; 1.0022x over previous
#include <cuda_runtime.h>
#include <cuda_bf16.h>
#include <math_constants.h>
#include <cstdint>

// Problem constants (reference: N=100000, E=1200000, all dims 128)
#define MAXN 100000
#define MAXE 1200000
#define MAXE2 (MAXE + MAXN)

// Scratch (device globals — allocation-free rule)
__device__ __align__(16) float g_xw[MAXN * 128];
__device__ __align__(16) float g_h[MAXN * 128];
__device__ __align__(16) float g_ssrc[MAXN * 4];
__device__ __align__(16) float g_sdst[MAXN * 4];
__device__ __align__(16) float g_alpha[MAXE2 * 4];

__device__ int g_counts[MAXN];
__device__ int g_cursor[MAXN];
__device__ int g_rowptr[MAXN + 1];
__device__ int g_csr[MAXE2];

// Pre-split weights: tf32 hi/lo (stored as fp32 bit patterns), transposed [n][k]
__device__ __align__(16) float g_Whi32[3 * 128 * 128];
__device__ __align__(16) float g_Wlo32[3 * 128 * 128];

// ---------------------------------------------------------------------------
__device__ __forceinline__ float to_tf32(float x) {
    uint32_t u;
    asm("cvt.rna.tf32.f32 %0, %1;" : "=r"(u) : "f"(x));
    return __uint_as_float(u);
}

__device__ __forceinline__ void mma_tf32(float* c, float2 a_lo, float2 a_hi, float2 b) {
    // a_lo = {a0 (row g,   col q), a2 (row g,   col q+4)}
    // a_hi = {a1 (row g+8, col q), a3 (row g+8, col q+4)}
    // b    = {b0 (k q, n g),       b1 (k q+4, n g)}
    asm("mma.sync.aligned.m16n8k8.row.col.f32.tf32.tf32.f32 "
        "{%0,%1,%2,%3}, {%4,%5,%6,%7}, {%8,%9}, {%0,%1,%2,%3};"
        : "+f"(c[0]), "+f"(c[1]), "+f"(c[2]), "+f"(c[3])
        : "r"(__float_as_uint(a_lo.x)), "r"(__float_as_uint(a_hi.x)),
          "r"(__float_as_uint(a_lo.y)), "r"(__float_as_uint(a_hi.y)),
          "r"(__float_as_uint(b.x)),    "r"(__float_as_uint(b.y)));
}

// Swizzled float2 slot: tile stored as float2[rows][64]; pair slot f holds
// k-columns (8*(f/4) + f%4, +4). Swizzle bits 2..3 of f by (row & 3).
__device__ __forceinline__ int slot_idx(int row, int f) {
    return row * 64 + (f ^ ((row & 3) << 2));
}

// ---------------------------------------------------------------------------
// Weight prep: W[k][n] fp32 -> tf32 hi/lo, transposed to [n][k]
// ---------------------------------------------------------------------------
__global__ void prep_w_k(const float* __restrict__ W0, const float* __restrict__ W1,
                         const float* __restrict__ W2)
{
    int i = blockIdx.x * blockDim.x + threadIdx.x;
    if (i >= 3 * 16384) return;
    int l = i >> 14, r = i & 16383;
    int k = r >> 7, nn = r & 127;
    const float* W = (l == 0) ? W0 : (l == 1) ? W1 : W2;
    float x = W[k * 128 + nn];
    float hi = to_tf32(x);
    g_Whi32[l * 16384 + nn * 128 + k] = hi;
    g_Wlo32[l * 16384 + nn * 128 + k] = to_tf32(x - hi);
}

// ---------------------------------------------------------------------------
// 3xTF32 GEMM: g_xw[64 rows/block, 128] = A @ W, with fused score epilogue
// (g_ssrc/g_sdst). Block: 128 threads (4 warps, each 32 rows x 64 cols).
// Smem: A_hi/A_lo (64x128) + W_hi/W_lo (128x128) = 192 KB, loaded once.
// ---------------------------------------------------------------------------
__global__ __launch_bounds__(128) void gemm_tf32_k(
    const float* __restrict__ A,
    const float* __restrict__ Whi, const float* __restrict__ Wlo,
    const float* __restrict__ as_, const float* __restrict__ ad_, int n)
{
    extern __shared__ float2 sm2[];
    float2* sAhi = sm2;                 // 64*64 float2
    float2* sAlo = sm2 + 64 * 64;
    float2* sWhi = sm2 + 2 * 64 * 64;   // 128*64 float2
    float2* sWlo = sm2 + 2 * 64 * 64 + 128 * 64;

    int tid = threadIdx.x;
    int wid = tid >> 5, lane = tid & 31;
    int row0 = blockIdx.x * 64;

    // Fill W tiles: 128 rows x 16 k-groups, both hi & lo
    #pragma unroll
    for (int it = 0; it < 16; it++) {
        int id = tid + it * 128;            // 0..2047
        int nr = id >> 4, g = id & 15;
        const float4* ph = (const float4*)(Whi + nr * 128 + g * 8);
        const float4* pl = (const float4*)(Wlo + nr * 128 + g * 8);
        float4 h1 = ph[0], h2 = ph[1];
        float4 l1 = pl[0], l2 = pl[1];
        sWhi[slot_idx(nr, 4 * g + 0)] = make_float2(h1.x, h2.x);
        sWhi[slot_idx(nr, 4 * g + 1)] = make_float2(h1.y, h2.y);
        sWhi[slot_idx(nr, 4 * g + 2)] = make_float2(h1.z, h2.z);
        sWhi[slot_idx(nr, 4 * g + 3)] = make_float2(h1.w, h2.w);
        sWlo[slot_idx(nr, 4 * g + 0)] = make_float2(l1.x, l2.x);
        sWlo[slot_idx(nr, 4 * g + 1)] = make_float2(l1.y, l2.y);
        sWlo[slot_idx(nr, 4 * g + 2)] = make_float2(l1.z, l2.z);
        sWlo[slot_idx(nr, 4 * g + 3)] = make_float2(l1.w, l2.w);
    }
    // Fill A tiles with tf32 split: 64 rows x 16 k-groups
    #pragma unroll
    for (int it = 0; it < 8; it++) {
        int id = tid + it * 128;            // 0..1023
        int r = id >> 4, g = id & 15;
        int grow = row0 + r;
        float4 v1 = make_float4(0.f, 0.f, 0.f, 0.f), v2 = v1;
        if (grow < n) {
            const float4* p = (const float4*)(A + (size_t)grow * 128 + g * 8);
            v1 = __ldg(p); v2 = __ldg(p + 1);
        }
        float h[8], l[8];
        float vv[8] = {v1.x, v1.y, v1.z, v1.w, v2.x, v2.y, v2.z, v2.w};
        #pragma unroll
        for (int c = 0; c < 8; c++) {
            h[c] = to_tf32(vv[c]);
            l[c] = to_tf32(vv[c] - h[c]);
        }
        #pragma unroll
        for (int c = 0; c < 4; c++) {
            sAhi[slot_idx(r, 4 * g + c)] = make_float2(h[c], h[c + 4]);
            sAlo[slot_idx(r, 4 * g + c)] = make_float2(l[c], l[c + 4]);
        }
    }
    __syncthreads();

    int q = lane & 3, g4 = lane >> 2;
    int wr = wid >> 1, wc = wid & 1;     // warp: rows wr*32.., cols wc*64..

    float acc[2][8][4];
    #pragma unroll
    for (int mt = 0; mt < 2; mt++)
        #pragma unroll
        for (int nt = 0; nt < 8; nt++)
            #pragma unroll
            for (int i = 0; i < 4; i++) acc[mt][nt][i] = 0.f;

    #pragma unroll
    for (int ks = 0; ks < 16; ks++) {
        int sx = 4 * (ks ^ (g4 & 3)) + q;     // swizzled f (row&3 == g4&3 for all operand rows)
        float2 ah[2][2], al[2][2];
        #pragma unroll
        for (int mt = 0; mt < 2; mt++) {
            int r0 = wr * 32 + mt * 16 + g4;
            ah[mt][0] = sAhi[r0 * 64 + sx];
            ah[mt][1] = sAhi[(r0 + 8) * 64 + sx];
            al[mt][0] = sAlo[r0 * 64 + sx];
            al[mt][1] = sAlo[(r0 + 8) * 64 + sx];
        }
        #pragma unroll
        for (int nt = 0; nt < 8; nt++) {
            int nr = wc * 64 + nt * 8 + g4;
            float2 bh = sWhi[nr * 64 + sx];
            float2 bl = sWlo[nr * 64 + sx];
            #pragma unroll
            for (int mt = 0; mt < 2; mt++) {
                mma_tf32(acc[mt][nt], ah[mt][0], ah[mt][1], bh);   // hi*hi
                mma_tf32(acc[mt][nt], al[mt][0], al[mt][1], bh);   // lo*hi
                mma_tf32(acc[mt][nt], ah[mt][0], ah[mt][1], bl);   // hi*lo
            }
        }
    }

    // Epilogue: write xw (float2, 32B-sector coalesced) + fused attn scores.
    // c layout: c0: (row, col), c1: (row, col+1), c2: (row+8, col), c3: (row+8, col+1)
    // with row = wr*32 + mt*16 + g4, col = wc*64 + nt*8 + q*2.
    float ps[2][2][2] = {}, pd[2][2][2] = {};   // [mt][rowsel][head-in-warp]
    #pragma unroll
    for (int mt = 0; mt < 2; mt++) {
        #pragma unroll
        for (int nt = 0; nt < 8; nt++) {
            int col = wc * 64 + nt * 8 + q * 2;
            float a0 = __ldg(as_ + col), a1 = __ldg(as_ + col + 1);
            float d0 = __ldg(ad_ + col), d1 = __ldg(ad_ + col + 1);
            int hs = nt >> 2;
            ps[mt][0][hs] += acc[mt][nt][0] * a0 + acc[mt][nt][1] * a1;
            pd[mt][0][hs] += acc[mt][nt][0] * d0 + acc[mt][nt][1] * d1;
            ps[mt][1][hs] += acc[mt][nt][2] * a0 + acc[mt][nt][3] * a1;
            pd[mt][1][hs] += acc[mt][nt][2] * d0 + acc[mt][nt][3] * d1;
            int r0 = row0 + wr * 32 + mt * 16 + g4;
            if (r0 < n)
                *(float2*)(g_xw + (size_t)r0 * 128 + col) =
                    make_float2(acc[mt][nt][0], acc[mt][nt][1]);
            if (r0 + 8 < n)
                *(float2*)(g_xw + (size_t)(r0 + 8) * 128 + col) =
                    make_float2(acc[mt][nt][2], acc[mt][nt][3]);
        }
    }
    // Quad reduce (lanes sharing g4)
    #pragma unroll
    for (int mt = 0; mt < 2; mt++)
        #pragma unroll
        for (int rs = 0; rs < 2; rs++)
            #pragma unroll
            for (int hs = 0; hs < 2; hs++) {
                float v = ps[mt][rs][hs];
                v += __shfl_xor_sync(0xffffffffu, v, 1);
                v += __shfl_xor_sync(0xffffffffu, v, 2);
                ps[mt][rs][hs] = v;
                float w = pd[mt][rs][hs];
                w += __shfl_xor_sync(0xffffffffu, w, 1);
                w += __shfl_xor_sync(0xffffffffu, w, 2);
                pd[mt][rs][hs] = w;
            }
    // q=0: ssrc head0, q=1: ssrc head1, q=2: sdst head0, q=3: sdst head1
    {
        int headG = wc * 2 + (q & 1);
        #pragma unroll
        for (int mt = 0; mt < 2; mt++)
            #pragma unroll
            for (int rs = 0; rs < 2; rs++) {
                int r = row0 + wr * 32 + mt * 16 + g4 + rs * 8;
                if (r < n) {
                    float v = (q < 2) ? ps[mt][rs][q & 1] : pd[mt][rs][q & 1];
                    float* dst = (q < 2) ? g_ssrc : g_sdst;
                    dst[(size_t)r * 4 + headG] = v;
                }
            }
    }
}

// ---------------------------------------------------------------------------
// CSR build (once; edge structure identical across layers)
// ---------------------------------------------------------------------------
__global__ void hist_k(const int* __restrict__ ei, int E, int E2)
{
    int e = blockIdx.x * blockDim.x + threadIdx.x;
    if (e >= E2) return;
    int d = (e < E) ? __ldg(ei + E + e) : (e - E);
    atomicAdd(g_counts + d, 1);
}

__global__ __launch_bounds__(1024) void scan_k(int n, int E2)
{
    __shared__ int warpsums[32];
    __shared__ int s_carry;
    int lane = threadIdx.x & 31, wid = threadIdx.x >> 5;
    if (threadIdx.x == 0) s_carry = 0;
    __syncthreads();

    for (int base = 0; base < n; base += 1024) {
        int i = base + threadIdx.x;
        int v = (i < n) ? g_counts[i] : 0;
        int x = v;
        #pragma unroll
        for (int off = 1; off < 32; off <<= 1) {
            int t = __shfl_up_sync(0xffffffffu, x, off);
            if (lane >= off) x += t;
        }
        if (lane == 31) warpsums[wid] = x;
        __syncthreads();
        if (wid == 0) {
            int ws = warpsums[lane];
            #pragma unroll
            for (int off = 1; off < 32; off <<= 1) {
                int t = __shfl_up_sync(0xffffffffu, ws, off);
                if (lane >= off) ws += t;
            }
            warpsums[lane] = ws;
        }
        __syncthreads();
        int incl = x + (wid > 0 ? warpsums[wid - 1] : 0);
        int carry = s_carry;
        if (i < n) {
            g_rowptr[i + 1] = carry + incl;
            g_cursor[i] = carry + incl - v;
        }
        __syncthreads();
        if (threadIdx.x == 1023) s_carry = carry + warpsums[31];
        __syncthreads();
    }
    if (threadIdx.x == 0) { g_rowptr[0] = 0; g_rowptr[n] = E2; }
}

__global__ void scatter_k(const int* __restrict__ ei, int E, int E2)
{
    int e = blockIdx.x * blockDim.x + threadIdx.x;
    if (e >= E2) return;
    int s, d;
    if (e < E) { s = __ldg(ei + e); d = __ldg(ei + E + e); }
    else       { s = d = e - E; }
    int pos = atomicAdd(g_cursor + d, 1);
    g_csr[pos] = s;
}

// ---------------------------------------------------------------------------
// Fused per-destination softmax + aggregation + epilogue. One warp per node.
// (No max subtraction: scores are O(1); exp/sum(exp) is shift-invariant.)
// ---------------------------------------------------------------------------
__global__ __launch_bounds__(256) void fused_gat_k(
    const float* __restrict__ bias, float* __restrict__ out, int n, int mode)
{
    int gid = blockIdx.x * blockDim.x + threadIdx.x;
    int node = gid >> 5, lane = gid & 31;
    if (node >= n) return;

    int beg = g_rowptr[node];
    int end = g_rowptr[node + 1];

    float4 sd = *(const float4*)(g_sdst + (size_t)node * 4);

    float4 den = make_float4(0.f, 0.f, 0.f, 0.f);
    for (int j = beg + lane; j < end; j += 32) {
        int s = g_csr[j];
        float4 ss = *(const float4*)(g_ssrc + (size_t)s * 4);
        float4 a;
        a.x = ss.x + sd.x; a.x = a.x > 0.f ? a.x : 0.2f * a.x;
        a.y = ss.y + sd.y; a.y = a.y > 0.f ? a.y : 0.2f * a.y;
        a.z = ss.z + sd.z; a.z = a.z > 0.f ? a.z : 0.2f * a.z;
        a.w = ss.w + sd.w; a.w = a.w > 0.f ? a.w : 0.2f * a.w;
        float4 ex;
        ex.x = expf(a.x); ex.y = expf(a.y); ex.z = expf(a.z); ex.w = expf(a.w);
        *(float4*)(g_alpha + (size_t)j * 4) = ex;
        den.x += ex.x; den.y += ex.y; den.z += ex.z; den.w += ex.w;
    }
    #pragma unroll
    for (int off = 16; off > 0; off >>= 1) {
        den.x += __shfl_xor_sync(0xffffffffu, den.x, off);
        den.y += __shfl_xor_sync(0xffffffffu, den.y, off);
        den.z += __shfl_xor_sync(0xffffffffu, den.z, off);
        den.w += __shfl_xor_sync(0xffffffffu, den.w, off);
    }

    int h = lane >> 3;
    float den_h = (h == 0) ? den.x : (h == 1) ? den.y : (h == 2) ? den.z : den.w;
    float inv = 1.0f / fmaxf(den_h, 1e-16f);

    float4 acc = make_float4(0.f, 0.f, 0.f, 0.f);
    #pragma unroll 4
    for (int j = beg; j < end; j++) {
        int s = g_csr[j];
        float at = g_alpha[(size_t)j * 4 + h] * inv;
        float4 v = *(const float4*)(g_xw + (size_t)s * 128 + lane * 4);
        acc.x = fmaf(v.x, at, acc.x);
        acc.y = fmaf(v.y, at, acc.y);
        acc.z = fmaf(v.z, at, acc.z);
        acc.w = fmaf(v.w, at, acc.w);
    }

    if (mode == 0) {
        float4 b = *(const float4*)(bias + lane * 4);
        float4 o;
        o.x = acc.x + b.x; o.x = o.x > 0.f ? o.x : (expf(o.x) - 1.f);
        o.y = acc.y + b.y; o.y = o.y > 0.f ? o.y : (expf(o.y) - 1.f);
        o.z = acc.z + b.z; o.z = o.z > 0.f ? o.z : (expf(o.z) - 1.f);
        o.w = acc.w + b.w; o.w = o.w > 0.f ? o.w : (expf(o.w) - 1.f);
        *(float4*)(out + (size_t)node * 128 + lane * 4) = o;
    } else {
        acc.x += __shfl_xor_sync(0xffffffffu, acc.x, 8);
        acc.y += __shfl_xor_sync(0xffffffffu, acc.y, 8);
        acc.z += __shfl_xor_sync(0xffffffffu, acc.z, 8);
        acc.w += __shfl_xor_sync(0xffffffffu, acc.w, 8);
        acc.x += __shfl_xor_sync(0xffffffffu, acc.x, 16);
        acc.y += __shfl_xor_sync(0xffffffffu, acc.y, 16);
        acc.z += __shfl_xor_sync(0xffffffffu, acc.z, 16);
        acc.w += __shfl_xor_sync(0xffffffffu, acc.w, 16);
        if (lane < 8) {
            float4 b = *(const float4*)(bias + lane * 4);
            float4 o;
            o.x = 0.25f * acc.x + b.x;
            o.y = 0.25f * acc.y + b.y;
            o.z = 0.25f * acc.z + b.z;
            o.w = 0.25f * acc.w + b.w;
            *(float4*)(out + (size_t)node * 32 + lane * 4) = o;
        }
    }
}

// ---------------------------------------------------------------------------
extern "C" void kernel_launch(void* const* d_in, const int* in_sizes, int n_in,
                              void* d_out, int out_size)
{
    const float* x  = (const float*)d_in[0];
    const int*   ei = (const int*)d_in[1];
    const float* W[3]  = {(const float*)d_in[2], (const float*)d_in[6],  (const float*)d_in[10]};
    const float* AS[3] = {(const float*)d_in[3], (const float*)d_in[7],  (const float*)d_in[11]};
    const float* AD[3] = {(const float*)d_in[4], (const float*)d_in[8],  (const float*)d_in[12]};
    const float* B[3]  = {(const float*)d_in[5], (const float*)d_in[9],  (const float*)d_in[13]};

    int n  = in_sizes[0] / 128;
    int E  = in_sizes[1] / 2;
    int E2 = E + n;

    float* hbuf = nullptr;
    cudaGetSymbolAddress((void**)&hbuf, g_h);
    int* counts_ptr = nullptr;
    cudaGetSymbolAddress((void**)&counts_ptr, g_counts);
    float* whi = nullptr;
    cudaGetSymbolAddress((void**)&whi, g_Whi32);
    float* wlo = nullptr;
    cudaGetSymbolAddress((void**)&wlo, g_Wlo32);

    const int SMEM_TC = (2 * 64 * 64 + 2 * 128 * 64) * 8;   // 196608 B = 192 KB
    cudaFuncSetAttribute(gemm_tf32_k, cudaFuncAttributeMaxDynamicSharedMemorySize, SMEM_TC);

    // Weight prep + CSR build
    prep_w_k<<<(3 * 16384 + 255) / 256, 256>>>(W[0], W[1], W[2]);
    cudaMemsetAsync(counts_ptr, 0, (size_t)n * sizeof(int));
    hist_k<<<(E2 + 255) / 256, 256>>>(ei, E, E2);
    scan_k<<<1, 1024>>>(n, E2);
    scatter_k<<<(E2 + 255) / 256, 256>>>(ei, E, E2);

    const float* in = x;
    for (int L = 0; L < 3; L++) {
        gemm_tf32_k<<<(n + 63) / 64, 128, SMEM_TC>>>(
            in, whi + L * 16384, wlo + L * 16384, AS[L], AD[L], n);
        if (L < 2) {
            fused_gat_k<<<(n * 32 + 255) / 256, 256>>>(B[L], hbuf, n, 0);
            in = hbuf;
        } else {
            fused_gat_k<<<(n * 32 + 255) / 256, 256>>>(B[2], (float*)d_out, n, 1);
        }
    }
}

// round 9
// speedup vs baseline: 1.3904x; 1.3818x over previous
#include <cuda_runtime.h>
#include <cuda_bf16.h>
#include <math_constants.h>
#include <cstdint>

// Problem constants (reference: N=100000, E=1200000, all dims 128)
#define MAXN 100000
#define MAXE 1200000
#define MAXE2 (MAXE + MAXN)

// Scratch (device globals — allocation-free rule)
__device__ __align__(16) float g_xw[MAXN * 128];     // x @ W            [N,128]
__device__ __align__(16) float g_h[MAXN * 128];      // layer output     [N,128]
__device__ __align__(16) float g_ssrc[MAXN * 4];
__device__ __align__(16) float g_sdst[MAXN * 4];

__device__ int g_counts[MAXN];
__device__ int g_cursor[MAXN];
__device__ int g_rowptr[MAXN + 1];
__device__ int g_csr[MAXE2];                          // src per CSR slot (dst-sorted)

// ---------------------------------------------------------------------------
// GEMM: g_xw[n,128] = A[n,128] @ W[128,128], with fused attention-score
// epilogue (g_ssrc/g_sdst). Block: 256 threads, tile 64 rows x 128 cols.
// ---------------------------------------------------------------------------
__global__ __launch_bounds__(256) void gemm128_k(
    const float* __restrict__ A, const float* __restrict__ W,
    const float* __restrict__ as_, const float* __restrict__ ad_, int n)
{
    extern __shared__ float sm[];
    float4* sA4 = (float4*)sm;               // 64 x 32 float4
    float4* sW4 = (float4*)(sm + 64 * 128);  // 128 x 32 float4

    int t = threadIdx.x;
    int row0 = blockIdx.x * 64;

    const float4* A4 = (const float4*)A;
    #pragma unroll
    for (int i = 0; i < 8; i++) {
        int idx = t + i * 256;
        int r = idx >> 5, c = idx & 31;
        float4 v = make_float4(0.f, 0.f, 0.f, 0.f);
        if (row0 + r < n) v = A4[(size_t)(row0 + r) * 32 + c];
        sA4[idx] = v;
    }
    const float4* W4 = (const float4*)W;
    #pragma unroll
    for (int i = 0; i < 16; i++) {
        int idx = t + i * 256;
        sW4[idx] = W4[idx];
    }
    __syncthreads();

    int tx = t & 31, ty = t >> 5;            // tx: col-group (4 cols), ty: warp
    float4 acc[8];
    #pragma unroll
    for (int i = 0; i < 8; i++) acc[i] = make_float4(0.f, 0.f, 0.f, 0.f);

    #pragma unroll
    for (int k4 = 0; k4 < 32; k4++) {
        float4 w0 = sW4[(4 * k4 + 0) * 32 + tx];
        float4 w1 = sW4[(4 * k4 + 1) * 32 + tx];
        float4 w2 = sW4[(4 * k4 + 2) * 32 + tx];
        float4 w3 = sW4[(4 * k4 + 3) * 32 + tx];
        #pragma unroll
        for (int i = 0; i < 8; i++) {
            float4 a = sA4[(i * 8 + ty) * 32 + k4];
            acc[i].x = fmaf(a.x, w0.x, fmaf(a.y, w1.x, fmaf(a.z, w2.x, fmaf(a.w, w3.x, acc[i].x))));
            acc[i].y = fmaf(a.x, w0.y, fmaf(a.y, w1.y, fmaf(a.z, w2.y, fmaf(a.w, w3.y, acc[i].y))));
            acc[i].z = fmaf(a.x, w0.z, fmaf(a.y, w1.z, fmaf(a.z, w2.z, fmaf(a.w, w3.z, acc[i].z))));
            acc[i].w = fmaf(a.x, w0.w, fmaf(a.y, w1.w, fmaf(a.z, w2.w, fmaf(a.w, w3.w, acc[i].w))));
        }
    }

    // Write xw
    float4* O4 = (float4*)g_xw;
    #pragma unroll
    for (int i = 0; i < 8; i++) {
        int r = row0 + i * 8 + ty;
        if (r < n) O4[(size_t)r * 32 + tx] = acc[i];
    }

    // Fused score epilogue: cols 4tx..4tx+3 all belong to head tx>>3.
    float4 av = __ldg((const float4*)as_ + tx);
    float4 dv = __ldg((const float4*)ad_ + tx);
    int head = tx >> 3;
    #pragma unroll
    for (int i = 0; i < 8; i++) {
        float ps = acc[i].x * av.x + acc[i].y * av.y + acc[i].z * av.z + acc[i].w * av.w;
        float pd = acc[i].x * dv.x + acc[i].y * dv.y + acc[i].z * dv.z + acc[i].w * dv.w;
        ps += __shfl_xor_sync(0xffffffffu, ps, 1);
        ps += __shfl_xor_sync(0xffffffffu, ps, 2);
        ps += __shfl_xor_sync(0xffffffffu, ps, 4);
        pd += __shfl_xor_sync(0xffffffffu, pd, 1);
        pd += __shfl_xor_sync(0xffffffffu, pd, 2);
        pd += __shfl_xor_sync(0xffffffffu, pd, 4);
        int r = row0 + i * 8 + ty;
        if ((tx & 7) == 0 && r < n) {
            g_ssrc[(size_t)r * 4 + head] = ps;
            g_sdst[(size_t)r * 4 + head] = pd;
        }
    }
}

// ---------------------------------------------------------------------------
// CSR build (once; edge structure identical across layers)
// ---------------------------------------------------------------------------
__global__ void hist_k(const int* __restrict__ ei, int E, int E2)
{
    int e = blockIdx.x * blockDim.x + threadIdx.x;
    if (e >= E2) return;
    int d = (e < E) ? __ldg(ei + E + e) : (e - E);
    atomicAdd(g_counts + d, 1);
}

__global__ __launch_bounds__(1024) void scan_k(int n, int E2)
{
    __shared__ int warpsums[32];
    __shared__ int s_carry;
    int lane = threadIdx.x & 31, wid = threadIdx.x >> 5;
    if (threadIdx.x == 0) s_carry = 0;
    __syncthreads();

    for (int base = 0; base < n; base += 1024) {
        int i = base + threadIdx.x;
        int v = (i < n) ? g_counts[i] : 0;
        int x = v;
        #pragma unroll
        for (int off = 1; off < 32; off <<= 1) {
            int t = __shfl_up_sync(0xffffffffu, x, off);
            if (lane >= off) x += t;
        }
        if (lane == 31) warpsums[wid] = x;
        __syncthreads();
        if (wid == 0) {
            int ws = warpsums[lane];
            #pragma unroll
            for (int off = 1; off < 32; off <<= 1) {
                int t = __shfl_up_sync(0xffffffffu, ws, off);
                if (lane >= off) ws += t;
            }
            warpsums[lane] = ws;
        }
        __syncthreads();
        int incl = x + (wid > 0 ? warpsums[wid - 1] : 0);
        int carry = s_carry;
        if (i < n) {
            g_rowptr[i + 1] = carry + incl;
            g_cursor[i] = carry + incl - v;
        }
        __syncthreads();
        if (threadIdx.x == 1023) s_carry = carry + warpsums[31];
        __syncthreads();
    }
    if (threadIdx.x == 0) { g_rowptr[0] = 0; g_rowptr[n] = E2; }
}

__global__ void scatter_k(const int* __restrict__ ei, int E, int E2)
{
    int e = blockIdx.x * blockDim.x + threadIdx.x;
    if (e >= E2) return;
    int s, d;
    if (e < E) { s = __ldg(ei + e); d = __ldg(ei + E + e); }
    else       { s = d = e - E; }
    int pos = atomicAdd(g_cursor + d, 1);
    g_csr[pos] = s;
}

// ---------------------------------------------------------------------------
// Single-pass fused softmax + aggregation. One warp per destination node.
// out = (sum_j ex_j * xw[src_j]) / (sum_j ex_j); no max shift (scores O(1)),
// no alpha scratch. All lanes compute ex redundantly (same MUFU warp-slots).
// mode 0: out = elu(agg + bias) [N,128];  mode 1: out = mean_heads(agg)+b [N,32]
// ---------------------------------------------------------------------------
__global__ __launch_bounds__(256) void fused_gat_k(
    const float* __restrict__ bias, float* __restrict__ out, int n, int mode)
{
    int gid = blockIdx.x * blockDim.x + threadIdx.x;
    int node = gid >> 5, lane = gid & 31;
    if (node >= n) return;

    int beg = g_rowptr[node];
    int end = g_rowptr[node + 1];
    int h = lane >> 3;

    float sd_h = g_sdst[(size_t)node * 4 + h];

    float den = 0.f;
    float4 acc = make_float4(0.f, 0.f, 0.f, 0.f);

    #pragma unroll 2
    for (int j = beg; j < end; j++) {
        int s = g_csr[j];                                  // warp-uniform
        float a = g_ssrc[(size_t)s * 4 + h] + sd_h;        // 8-way broadcast
        a = a > 0.f ? a : 0.2f * a;
        float ex = __expf(a);
        den += ex;
        float4 v = *(const float4*)(g_xw + (size_t)s * 128 + lane * 4);
        acc.x = fmaf(v.x, ex, acc.x);
        acc.y = fmaf(v.y, ex, acc.y);
        acc.z = fmaf(v.z, ex, acc.z);
        acc.w = fmaf(v.w, ex, acc.w);
    }

    float inv = 1.0f / fmaxf(den, 1e-16f);
    acc.x *= inv; acc.y *= inv; acc.z *= inv; acc.w *= inv;

    if (mode == 0) {
        float4 b = *(const float4*)(bias + lane * 4);
        float4 o;
        o.x = acc.x + b.x; o.x = o.x > 0.f ? o.x : (expf(o.x) - 1.f);
        o.y = acc.y + b.y; o.y = o.y > 0.f ? o.y : (expf(o.y) - 1.f);
        o.z = acc.z + b.z; o.z = o.z > 0.f ? o.z : (expf(o.z) - 1.f);
        o.w = acc.w + b.w; o.w = o.w > 0.f ? o.w : (expf(o.w) - 1.f);
        *(float4*)(out + (size_t)node * 128 + lane * 4) = o;
    } else {
        // mean over 4 heads: lanes {l, l^8, l^16, l^24} hold same feature group
        acc.x += __shfl_xor_sync(0xffffffffu, acc.x, 8);
        acc.y += __shfl_xor_sync(0xffffffffu, acc.y, 8);
        acc.z += __shfl_xor_sync(0xffffffffu, acc.z, 8);
        acc.w += __shfl_xor_sync(0xffffffffu, acc.w, 8);
        acc.x += __shfl_xor_sync(0xffffffffu, acc.x, 16);
        acc.y += __shfl_xor_sync(0xffffffffu, acc.y, 16);
        acc.z += __shfl_xor_sync(0xffffffffu, acc.z, 16);
        acc.w += __shfl_xor_sync(0xffffffffu, acc.w, 16);
        if (lane < 8) {
            float4 b = *(const float4*)(bias + lane * 4);
            float4 o;
            o.x = 0.25f * acc.x + b.x;
            o.y = 0.25f * acc.y + b.y;
            o.z = 0.25f * acc.z + b.z;
            o.w = 0.25f * acc.w + b.w;
            *(float4*)(out + (size_t)node * 32 + lane * 4) = o;
        }
    }
}

// ---------------------------------------------------------------------------
extern "C" void kernel_launch(void* const* d_in, const int* in_sizes, int n_in,
                              void* d_out, int out_size)
{
    const float* x  = (const float*)d_in[0];
    const int*   ei = (const int*)d_in[1];
    const float* W[3]  = {(const float*)d_in[2], (const float*)d_in[6],  (const float*)d_in[10]};
    const float* AS[3] = {(const float*)d_in[3], (const float*)d_in[7],  (const float*)d_in[11]};
    const float* AD[3] = {(const float*)d_in[4], (const float*)d_in[8],  (const float*)d_in[12]};
    const float* B[3]  = {(const float*)d_in[5], (const float*)d_in[9],  (const float*)d_in[13]};

    int n  = in_sizes[0] / 128;
    int E  = in_sizes[1] / 2;
    int E2 = E + n;

    float* hbuf = nullptr;
    cudaGetSymbolAddress((void**)&hbuf, g_h);
    int* counts_ptr = nullptr;
    cudaGetSymbolAddress((void**)&counts_ptr, g_counts);

    const int SMEM = (64 * 128 + 128 * 128) * (int)sizeof(float);  // 96 KB
    cudaFuncSetAttribute(gemm128_k, cudaFuncAttributeMaxDynamicSharedMemorySize, SMEM);

    // CSR build (edge structure shared by all 3 layers)
    cudaMemsetAsync(counts_ptr, 0, (size_t)n * sizeof(int));
    hist_k<<<(E2 + 255) / 256, 256>>>(ei, E, E2);
    scan_k<<<1, 1024>>>(n, E2);
    scatter_k<<<(E2 + 255) / 256, 256>>>(ei, E, E2);

    const float* in = x;
    for (int L = 0; L < 3; L++) {
        gemm128_k<<<(n + 63) / 64, 256, SMEM>>>(in, W[L], AS[L], AD[L], n);
        if (L < 2) {
            fused_gat_k<<<(n * 32 + 255) / 256, 256>>>(B[L], hbuf, n, 0);
            in = hbuf;
        } else {
            fused_gat_k<<<(n * 32 + 255) / 256, 256>>>(B[2], (float*)d_out, n, 1);
        }
    }
}